// round 2
// baseline (speedup 1.0000x reference)
#include <cuda_runtime.h>
#include <math.h>

#define N 1536
#define EE 24576
#define E2 (EE + N)
#define HD 128
#define DD 1280
#define NW 48   // N/32 bitmask words per row

// ---------------- device scratch (no allocations allowed) ----------------
__device__ float g_wa[HD], g_wb[HD], g_c2[N];
__device__ float g_sa[N], g_da[N];
__device__ float g_U[HD * N];          // (128,1536)
__device__ float g_G[N * N];           // x@U + c2  (9.4 MB)
__device__ float g_H2[N * N];          // P@G       (9.4 MB)
__device__ int   g_cntT[N], g_offT[N + 1], g_curT[N];
__device__ int   g_cntS[N], g_offS[N + 1], g_curS[N];
__device__ int   g_srcT[E2];           // CSR by target (incl self loops): src per entry
__device__ float g_alphaT[E2];         // GAT-1 softmax weights, aligned with g_srcT
__device__ int   g_tgtS[EE];           // CSR by source (original edges): tgt per entry
__device__ unsigned g_B[N * NW];       // B[t] = {s : edge s->t}
__device__ unsigned g_Mb[N * NW];      // 2-hop reachability row masks

__device__ __forceinline__ float lrelu(float v) { return v > 0.f ? v : 0.2f * v; }
// order-preserving float<->uint encode for atomicMax on shared memory
__device__ __forceinline__ unsigned fenc(float f) {
  unsigned u = __float_as_uint(f);
  return (u & 0x80000000u) ? ~u : (u | 0x80000000u);
}
__device__ __forceinline__ float fdec(unsigned u) {
  return (u & 0x80000000u) ? __uint_as_float(u & 0x7FFFFFFFu) : __uint_as_float(~u);
}
#define ENC_NEG_INF 0x007FFFFFu  // fenc(-inf)

__device__ __forceinline__ float blockSum(float v, float* sh) {
  __syncthreads();
  #pragma unroll
  for (int o = 16; o; o >>= 1) v += __shfl_xor_sync(0xFFFFFFFFu, v, o);
  if ((threadIdx.x & 31) == 0) sh[threadIdx.x >> 5] = v;
  __syncthreads();
  if (threadIdx.x < 32) {
    v = (threadIdx.x < (blockDim.x >> 5)) ? sh[threadIdx.x] : 0.f;
    #pragma unroll
    for (int o = 4; o; o >>= 1) v += __shfl_xor_sync(0xFFFFFFFFu, v, o);
  }
  return v;
}

// ---------------- K0: zero scratch that is accumulated into ----------------
__global__ void k_zero() {
  int i = blockIdx.x * blockDim.x + threadIdx.x;
  int stride = gridDim.x * blockDim.x;
  for (int p = i; p < HD * N; p += stride) g_U[p] = 0.f;
  for (int p = i; p < N * NW; p += stride) g_B[p] = 0u;
  for (int p = i; p < N; p += stride) { g_cntT[p] = 0; g_cntS[p] = 0; }
}

// ---------------- K1: wa = W1@a_src1, wb = W1@a_dst1, c2[j] = sum_d b1*w2*xo ----
__global__ void k_vec1(const float* __restrict__ W1, const float* __restrict__ a1,
                       const float* __restrict__ a2, const float* __restrict__ b1,
                       const float* __restrict__ w2, const float* __restrict__ xo) {
  __shared__ float sh[8];
  int b = blockIdx.x, tid = threadIdx.x;
  if (b < HD) {
    float s1 = 0.f, s2 = 0.f;
    for (int d = tid; d < DD; d += 256) {
      float w = W1[b * DD + d];
      s1 += w * a1[d]; s2 += w * a2[d];
    }
    float r1 = blockSum(s1, sh);
    float r2 = blockSum(s2, sh);
    if (tid == 0) { g_wa[b] = r1; g_wb[b] = r2; }
  } else {
    int j = b - HD;
    float s = 0.f;
    for (int d = tid; d < DD; d += 256) s += b1[d] * w2[d] * xo[j * DD + d];
    float r = blockSum(s, sh);
    if (tid == 0) g_c2[j] = r;
  }
}

// ---------------- K2: sa = x@wa, da = x@wb (warp per node) ----------------
__global__ void k_sada(const float* __restrict__ x) {
  int w = (blockIdx.x * blockDim.x + threadIdx.x) >> 5;
  int lane = threadIdx.x & 31;
  if (w >= N) return;
  float s1 = 0.f, s2 = 0.f;
  #pragma unroll
  for (int k = lane; k < HD; k += 32) {
    float xv = x[w * HD + k];
    s1 += xv * g_wa[k]; s2 += xv * g_wb[k];
  }
  #pragma unroll
  for (int o = 16; o; o >>= 1) {
    s1 += __shfl_xor_sync(0xFFFFFFFFu, s1, o);
    s2 += __shfl_xor_sync(0xFFFFFFFFu, s2, o);
  }
  if (lane == 0) { g_sa[w] = s1; g_da[w] = s2; }
}

// ---------------- K3: U = (W1 .* w2) @ xo^T  (split-K over grid.y, atomicAdd) ----
__global__ __launch_bounds__(256) void k_U(const float* __restrict__ W1,
                                           const float* __restrict__ w2,
                                           const float* __restrict__ xo) {
  __shared__ float As[128][33];  // [k][dd]
  __shared__ float Bs[128][33];  // [j][dd]
  int j0 = blockIdx.x * 128, d0 = blockIdx.y * 128;
  int tid = threadIdx.x, tx = tid & 15, ty = tid >> 4;
  float acc[8][8];
  #pragma unroll
  for (int u = 0; u < 8; u++)
    #pragma unroll
    for (int w = 0; w < 8; w++) acc[u][w] = 0.f;
  for (int dc = 0; dc < 128; dc += 32) {
    for (int l = tid; l < 128 * 32; l += 256) {
      int r = l >> 5, c = l & 31;
      As[r][c] = W1[r * DD + d0 + dc + c] * w2[d0 + dc + c];
      Bs[r][c] = xo[(j0 + r) * DD + d0 + dc + c];
    }
    __syncthreads();
    #pragma unroll
    for (int dd = 0; dd < 32; dd++) {
      float ra[8], rb[8];
      #pragma unroll
      for (int u = 0; u < 8; u++) ra[u] = As[ty * 8 + u][dd];
      #pragma unroll
      for (int w = 0; w < 8; w++) rb[w] = Bs[tx * 8 + w][dd];
      #pragma unroll
      for (int u = 0; u < 8; u++)
        #pragma unroll
        for (int w = 0; w < 8; w++) acc[u][w] += ra[u] * rb[w];
    }
    __syncthreads();
  }
  #pragma unroll
  for (int u = 0; u < 8; u++)
    #pragma unroll
    for (int w = 0; w < 8; w++)
      atomicAdd(&g_U[(ty * 8 + u) * N + j0 + tx * 8 + w], acc[u][w]);
}

// ---------------- K4: G = x @ U + c2 ----------------
__global__ __launch_bounds__(256) void k_G(const float* __restrict__ x) {
  __shared__ float As[128][33];   // [n][k]
  __shared__ float Bs[32][129];   // [k][j]
  int j0 = blockIdx.x * 128, n0 = blockIdx.y * 128;
  int tid = threadIdx.x, tx = tid & 15, ty = tid >> 4;
  float acc[8][8];
  #pragma unroll
  for (int u = 0; u < 8; u++)
    #pragma unroll
    for (int w = 0; w < 8; w++) acc[u][w] = 0.f;
  for (int kc = 0; kc < HD; kc += 32) {
    for (int l = tid; l < 128 * 32; l += 256) {
      int r = l >> 5, c = l & 31;
      As[r][c] = x[(n0 + r) * HD + kc + c];
    }
    for (int l = tid; l < 32 * 128; l += 256) {
      int r = l >> 7, c = l & 127;
      Bs[r][c] = g_U[(kc + r) * N + j0 + c];
    }
    __syncthreads();
    #pragma unroll
    for (int kk = 0; kk < 32; kk++) {
      float ra[8], rb[8];
      #pragma unroll
      for (int u = 0; u < 8; u++) ra[u] = As[ty * 8 + u][kk];
      #pragma unroll
      for (int w = 0; w < 8; w++) rb[w] = Bs[kk][tx * 8 + w];
      #pragma unroll
      for (int u = 0; u < 8; u++)
        #pragma unroll
        for (int w = 0; w < 8; w++) acc[u][w] += ra[u] * rb[w];
    }
    __syncthreads();
  }
  #pragma unroll
  for (int u = 0; u < 8; u++)
    #pragma unroll
    for (int w = 0; w < 8; w++)
      g_G[(n0 + ty * 8 + u) * N + j0 + tx * 8 + w] = acc[u][w] + g_c2[j0 + tx * 8 + w];
}

// ---------------- K5a/b/c: CSR construction ----------------
__global__ void k_count(const int* __restrict__ ei) {
  int idx = blockIdx.x * blockDim.x + threadIdx.x;
  if (idx >= E2) return;
  int t;
  if (idx < EE) { t = ei[EE + idx]; atomicAdd(&g_cntS[ei[idx]], 1); }
  else t = idx - EE;
  atomicAdd(&g_cntT[t], 1);
}

__global__ void k_scan() {
  __shared__ int part[512];
  int tid = threadIdx.x;
  int b = tid * 3;
  // targets
  {
    int a0 = g_cntT[b], a1 = g_cntT[b + 1], a2 = g_cntT[b + 2];
    int s = a0 + a1 + a2;
    part[tid] = s;
    __syncthreads();
    for (int o = 1; o < 512; o <<= 1) {
      int v = (tid >= o) ? part[tid - o] : 0;
      __syncthreads();
      part[tid] += v;
      __syncthreads();
    }
    int excl = part[tid] - s;
    g_offT[b] = excl;         g_curT[b] = excl;
    g_offT[b + 1] = excl + a0; g_curT[b + 1] = excl + a0;
    g_offT[b + 2] = excl + a0 + a1; g_curT[b + 2] = excl + a0 + a1;
    if (tid == 511) g_offT[N] = part[511];
    __syncthreads();
  }
  // sources
  {
    int a0 = g_cntS[b], a1 = g_cntS[b + 1], a2 = g_cntS[b + 2];
    int s = a0 + a1 + a2;
    part[tid] = s;
    __syncthreads();
    for (int o = 1; o < 512; o <<= 1) {
      int v = (tid >= o) ? part[tid - o] : 0;
      __syncthreads();
      part[tid] += v;
      __syncthreads();
    }
    int excl = part[tid] - s;
    g_offS[b] = excl;         g_curS[b] = excl;
    g_offS[b + 1] = excl + a0; g_curS[b + 1] = excl + a0;
    g_offS[b + 2] = excl + a0 + a1; g_curS[b + 2] = excl + a0 + a1;
    if (tid == 511) g_offS[N] = part[511];
  }
}

__global__ void k_fill(const int* __restrict__ ei) {
  int idx = blockIdx.x * blockDim.x + threadIdx.x;
  if (idx >= E2) return;
  int s, t;
  if (idx < EE) { s = ei[idx]; t = ei[EE + idx]; }
  else { s = t = idx - EE; }
  int pos = atomicAdd(&g_curT[t], 1);
  g_srcT[pos] = s;
  if (idx < EE) {
    int ps = atomicAdd(&g_curS[s], 1);
    g_tgtS[ps] = t;
  }
}

// ---------------- K6: GAT-1 segment softmax -> alpha (warp per target) ------
__global__ void k_alpha() {
  int t = (blockIdx.x * blockDim.x + threadIdx.x) >> 5;
  int lane = threadIdx.x & 31;
  if (t >= N) return;
  int p0 = g_offT[t], p1 = g_offT[t + 1];
  float dt = g_da[t];
  float m = -3.4e38f;
  for (int p = p0 + lane; p < p1; p += 32)
    m = fmaxf(m, lrelu(g_sa[g_srcT[p]] + dt));
  #pragma unroll
  for (int o = 16; o; o >>= 1) m = fmaxf(m, __shfl_xor_sync(0xFFFFFFFFu, m, o));
  float den = 0.f;
  for (int p = p0 + lane; p < p1; p += 32) {
    float e = lrelu(g_sa[g_srcT[p]] + dt);
    float w = expf(e - m);
    g_alphaT[p] = w;
    den += w;
  }
  #pragma unroll
  for (int o = 16; o; o >>= 1) den += __shfl_xor_sync(0xFFFFFFFFu, den, o);
  float inv = 1.f / den;
  for (int p = p0 + lane; p < p1; p += 32) g_alphaT[p] *= inv;
}

// ---------------- K7: H2[t,:] = sum_p alpha_p * G[src_p,:] ----------------
__global__ __launch_bounds__(256) void k_H2() {
  int t = blockIdx.x;
  int p0 = g_offT[t], p1 = g_offT[t + 1];
  __shared__ int ss[64];
  __shared__ float sal[64];
  float acc[6];
  #pragma unroll
  for (int c = 0; c < 6; c++) acc[c] = 0.f;
  for (int base = p0; base < p1; base += 64) {
    int nchunk = min(64, p1 - base);
    if (threadIdx.x < nchunk) {
      ss[threadIdx.x] = g_srcT[base + threadIdx.x];
      sal[threadIdx.x] = g_alphaT[base + threadIdx.x];
    }
    __syncthreads();
    for (int q = 0; q < nchunk; q++) {
      int s = ss[q]; float a = sal[q];
      const float* Gr = &g_G[s * N];
      #pragma unroll
      for (int c = 0; c < 6; c++) acc[c] += a * Gr[threadIdx.x + c * 256];
    }
    __syncthreads();
  }
  #pragma unroll
  for (int c = 0; c < 6; c++) g_H2[t * N + threadIdx.x + c * 256] = acc[c];
}

// ---------------- K8: reachability masks ----------------
__global__ void k_B(const int* __restrict__ ei) {
  int e = blockIdx.x * blockDim.x + threadIdx.x;
  if (e >= EE) return;
  int s = ei[e], t = ei[EE + e];
  atomicOr(&g_B[t * NW + (s >> 5)], 1u << (s & 31));
}

__global__ void k_Mb() {
  int i = blockIdx.x;
  __shared__ unsigned m1[NW];
  __shared__ int klist[N];
  __shared__ int nk;
  int tid = threadIdx.x;
  if (tid == 0) nk = 0;
  if (tid < NW) {
    unsigned w = g_B[i * NW + tid];
    if (tid == (i >> 5)) w |= 1u << (i & 31);
    m1[tid] = w;
  }
  __syncthreads();
  if (tid < NW) {
    unsigned w = m1[tid];
    while (w) {
      int b = __ffs(w) - 1;
      w &= w - 1;
      klist[atomicAdd(&nk, 1)] = tid * 32 + b;
    }
  }
  __syncthreads();
  int n = nk;
  if (tid < NW) {
    unsigned acc = m1[tid];
    for (int q = 0; q < n; q++) acc |= g_B[klist[q] * NW + tid];
    g_Mb[i * NW + tid] = acc;
  }
}

// ---------------- K9: per-row attention + top-k + output ----------------
__global__ __launch_bounds__(256) void k_row(const float* __restrict__ pas2,
                                             const float* __restrict__ pad2,
                                             const float* __restrict__ pb2,
                                             float* __restrict__ out, int wk) {
  int i = blockIdx.x, tid = threadIdx.x;
  __shared__ float v[N];
  __shared__ unsigned m2[N];
  __shared__ float den[N];
  __shared__ float num[N];
  __shared__ int vlist[N];
  __shared__ unsigned mb[NW];
  __shared__ int nv;
  float as2 = pas2[0], ad2 = pad2[0], b2 = pb2[0];
  if (tid == 0) nv = 0;
  if (tid < NW) mb[tid] = g_Mb[i * NW + tid];
  for (int j = tid; j < N; j += 256) {
    v[j] = g_H2[i * N + j];
    m2[j] = ENC_NEG_INF;
    den[j] = 0.f;
    num[j] = 0.f;
    out[i * N + j] = 0.f;
  }
  if (wk)
    for (int j = tid; j < N; j += 256) out[N * N + i * N + j] = 0.f;
  __syncthreads();
  // collect valid nodes
  for (int w = tid; w < NW; w += 256) {
    unsigned b = mb[w];
    while (b) {
      int t = __ffs(b) - 1;
      b &= b - 1;
      vlist[atomicAdd(&nv, 1)] = w * 32 + t;
    }
  }
  __syncthreads();
  int nvv = nv;
  // pass A: per-target max over valid edges (self-loops + out-edges of valid k)
  for (int li = tid; li < nvv; li += 256) {
    int k = vlist[li];
    float vk = v[k];
    atomicMax(&m2[k], fenc(lrelu((as2 + ad2) * vk)));
    int p0 = g_offS[k], p1 = g_offS[k + 1];
    for (int p = p0; p < p1; p++) {
      int t = g_tgtS[p];
      if ((mb[t >> 5] >> (t & 31)) & 1u) {
        float e = lrelu(as2 * vk + ad2 * v[t]);
        atomicMax(&m2[t], fenc(e));
      }
    }
  }
  __syncthreads();
  // pass B: exp-sum and weighted sum
  for (int li = tid; li < nvv; li += 256) {
    int k = vlist[li];
    float vk = v[k];
    {
      float e = lrelu((as2 + ad2) * vk);
      float w = expf(e - fdec(m2[k]));
      atomicAdd(&den[k], w);
      atomicAdd(&num[k], w * vk);
    }
    int p0 = g_offS[k], p1 = g_offS[k + 1];
    for (int p = p0; p < p1; p++) {
      int t = g_tgtS[p];
      if ((mb[t >> 5] >> (t & 31)) & 1u) {
        float e = lrelu(as2 * vk + ad2 * v[t]);
        float w = expf(e - fdec(m2[t]));
        atomicAdd(&den[t], w);
        atomicAdd(&num[t], w * vk);
      }
    }
  }
  __syncthreads();
  // scores (reuse v)
  for (int li = tid; li < nvv; li += 256) {
    int j = vlist[li];
    v[j] = num[j] / fmaxf(den[j], 1e-12f) + b2;
  }
  __syncthreads();
  // exact rank with stable tie-break by index, then write kept entries
  int kk = (nvv + 1) >> 1;  // ceil(0.5*size)
  for (int li = tid; li < nvv; li += 256) {
    int j = vlist[li];
    float sj = v[j];
    int cnt = 0;
    for (int p = 0; p < nvv; p++) {
      int j2 = vlist[p];
      float s2 = v[j2];
      cnt += (s2 > sj) || ((s2 == sj) && (j2 < j));
    }
    if (cnt < kk) {
      out[i * N + j] = 1.f / (1.f + expf(-sj));
      if (wk) out[N * N + i * N + j] = 1.f;
    }
  }
}

// ---------------- launch ----------------
extern "C" void kernel_launch(void* const* d_in, const int* in_sizes, int n_in,
                              void* d_out, int out_size) {
  const float* x   = (const float*)d_in[0];
  const float* xo  = (const float*)d_in[1];
  const int*   ei  = (const int*)d_in[2];
  const float* W1  = (const float*)d_in[4];
  const float* a1  = (const float*)d_in[5];
  const float* a2  = (const float*)d_in[6];
  const float* b1  = (const float*)d_in[7];
  const float* w2  = (const float*)d_in[8];
  const float* as2 = (const float*)d_in[9];
  const float* ad2 = (const float*)d_in[10];
  const float* b2  = (const float*)d_in[11];
  float* out = (float*)d_out;
  int wk = (out_size >= 2 * N * N) ? 1 : 0;

  k_zero<<<256, 256>>>();
  k_vec1<<<HD + N, 256>>>(W1, a1, a2, b1, w2, xo);
  k_sada<<<(N * 32) / 128, 128>>>(x);
  k_U<<<dim3(12, 10), 256>>>(W1, w2, xo);
  k_G<<<dim3(12, 12), 256>>>(x);
  k_count<<<(E2 + 255) / 256, 256>>>(ei);
  k_scan<<<1, 512>>>();
  k_fill<<<(E2 + 255) / 256, 256>>>(ei);
  k_alpha<<<(N * 32) / 128, 128>>>();
  k_H2<<<N, 256>>>();
  k_B<<<(EE + 255) / 256, 256>>>(ei);
  k_Mb<<<N, 64>>>();
  k_row<<<N, 256>>>(as2, ad2, b2, out, wk);
}

// round 3
// speedup vs baseline: 1.1555x; 1.1555x over previous
#include <cuda_runtime.h>
#include <math.h>

#define N 1536
#define EE 24576
#define E2 (EE + N)
#define HD 128
#define DD 1280
#define NW 48   // N/32 bitmask words per row

// ---------------- device scratch (no allocations allowed) ----------------
__device__ float g_wa[HD], g_wb[HD], g_c2[N];
__device__ float g_sa[N], g_da[N];
__device__ float g_U[HD * N];          // (128,1536)
__device__ float g_xg[N * HD];         // P @ x  (GAT-1 aggregated features)
__device__ float g_H2[N * N];          // xg @ U + c2  (9.4 MB)
__device__ int   g_cntT[N], g_offT[N + 1], g_curT[N];
__device__ int   g_cntS[N], g_offS[N + 1], g_curS[N];
__device__ int   g_srcT[E2];           // CSR by target (incl self loops): src per entry
__device__ int   g_tgtS[EE];           // CSR by source (original edges): tgt per entry
__device__ unsigned g_B[N * NW];       // B[t] = {s : edge s->t}
__device__ unsigned g_Mb[N * NW];      // 2-hop reachability row masks

__device__ __forceinline__ float lrelu(float v) { return v > 0.f ? v : 0.2f * v; }
// order-preserving float<->uint encode for atomicMax on shared memory
__device__ __forceinline__ unsigned fenc(float f) {
  unsigned u = __float_as_uint(f);
  return (u & 0x80000000u) ? ~u : (u | 0x80000000u);
}
__device__ __forceinline__ float fdec(unsigned u) {
  return (u & 0x80000000u) ? __uint_as_float(u & 0x7FFFFFFFu) : __uint_as_float(~u);
}
#define ENC_NEG_INF 0x007FFFFFu  // fenc(-inf)

__device__ __forceinline__ float blockSum(float v, float* sh) {
  __syncthreads();
  #pragma unroll
  for (int o = 16; o; o >>= 1) v += __shfl_xor_sync(0xFFFFFFFFu, v, o);
  if ((threadIdx.x & 31) == 0) sh[threadIdx.x >> 5] = v;
  __syncthreads();
  if (threadIdx.x < 32) {
    v = (threadIdx.x < (blockDim.x >> 5)) ? sh[threadIdx.x] : 0.f;
    #pragma unroll
    for (int o = 4; o; o >>= 1) v += __shfl_xor_sync(0xFFFFFFFFu, v, o);
  }
  return v;
}

// ---------------- K0: zero scratch that is accumulated into ----------------
__global__ void k_zero() {
  int i = blockIdx.x * blockDim.x + threadIdx.x;
  int stride = gridDim.x * blockDim.x;
  for (int p = i; p < HD * N; p += stride) g_U[p] = 0.f;
  for (int p = i; p < N * NW; p += stride) g_B[p] = 0u;
  for (int p = i; p < N; p += stride) { g_cntT[p] = 0; g_cntS[p] = 0; }
}

// ---------------- K1: wa = W1@a_src1, wb = W1@a_dst1, c2[j] = sum_d b1*w2*xo ----
__global__ void k_vec1(const float* __restrict__ W1, const float* __restrict__ a1,
                       const float* __restrict__ a2, const float* __restrict__ b1,
                       const float* __restrict__ w2, const float* __restrict__ xo) {
  __shared__ float sh[8];
  int b = blockIdx.x, tid = threadIdx.x;
  if (b < HD) {
    float s1 = 0.f, s2 = 0.f;
    for (int d = tid; d < DD; d += 256) {
      float w = W1[b * DD + d];
      s1 += w * a1[d]; s2 += w * a2[d];
    }
    float r1 = blockSum(s1, sh);
    float r2 = blockSum(s2, sh);
    if (tid == 0) { g_wa[b] = r1; g_wb[b] = r2; }
  } else {
    int j = b - HD;
    float s = 0.f;
    for (int d = tid; d < DD; d += 256) s += b1[d] * w2[d] * xo[j * DD + d];
    float r = blockSum(s, sh);
    if (tid == 0) g_c2[j] = r;
  }
}

// ---------------- K2: sa = x@wa, da = x@wb (warp per node) ----------------
__global__ void k_sada(const float* __restrict__ x) {
  int w = (blockIdx.x * blockDim.x + threadIdx.x) >> 5;
  int lane = threadIdx.x & 31;
  if (w >= N) return;
  float s1 = 0.f, s2 = 0.f;
  #pragma unroll
  for (int k = lane; k < HD; k += 32) {
    float xv = x[w * HD + k];
    s1 += xv * g_wa[k]; s2 += xv * g_wb[k];
  }
  #pragma unroll
  for (int o = 16; o; o >>= 1) {
    s1 += __shfl_xor_sync(0xFFFFFFFFu, s1, o);
    s2 += __shfl_xor_sync(0xFFFFFFFFu, s2, o);
  }
  if (lane == 0) { g_sa[w] = s1; g_da[w] = s2; }
}

// ---------------- K3: U = (W1 .* w2) @ xo^T (64x128 tiles, split-K atomics) ----
__global__ __launch_bounds__(256) void k_U(const float* __restrict__ W1,
                                           const float* __restrict__ w2,
                                           const float* __restrict__ xo) {
  __shared__ float As[32][65];    // [k][m]
  __shared__ float Bs[32][129];   // [k][j]
  int j0 = blockIdx.x * 128;
  int m0 = blockIdx.y * 64;
  int k0 = blockIdx.z * 128;
  int tid = threadIdx.x, tx = tid & 15, ty = tid >> 4;
  float acc[4][8];
  #pragma unroll
  for (int u = 0; u < 4; u++)
    #pragma unroll
    for (int w = 0; w < 8; w++) acc[u][w] = 0.f;
  for (int kc = 0; kc < 128; kc += 32) {
    #pragma unroll
    for (int l = tid; l < 64 * 32; l += 256) {
      int k = l & 31, m = l >> 5;
      As[k][m] = W1[(m0 + m) * DD + k0 + kc + k] * w2[k0 + kc + k];
    }
    #pragma unroll
    for (int l = tid; l < 128 * 32; l += 256) {
      int k = l & 31, j = l >> 5;
      Bs[k][j] = xo[(j0 + j) * DD + k0 + kc + k];
    }
    __syncthreads();
    #pragma unroll
    for (int kk = 0; kk < 32; kk++) {
      float ra[4], rb[8];
      #pragma unroll
      for (int u = 0; u < 4; u++) ra[u] = As[kk][u * 16 + ty];
      #pragma unroll
      for (int w = 0; w < 8; w++) rb[w] = Bs[kk][w * 16 + tx];
      #pragma unroll
      for (int u = 0; u < 4; u++)
        #pragma unroll
        for (int w = 0; w < 8; w++) acc[u][w] += ra[u] * rb[w];
    }
    __syncthreads();
  }
  #pragma unroll
  for (int u = 0; u < 4; u++)
    #pragma unroll
    for (int w = 0; w < 8; w++)
      atomicAdd(&g_U[(m0 + u * 16 + ty) * N + j0 + w * 16 + tx], acc[u][w]);
}

// ---------------- K4: H2 = xg @ U + c2 (64x128 tiles) ----------------
__global__ __launch_bounds__(256) void k_H2g() {
  __shared__ float As[32][65];    // [k][m]
  __shared__ float Bs[32][129];   // [k][j]
  int j0 = blockIdx.x * 128;
  int m0 = blockIdx.y * 64;
  int tid = threadIdx.x, tx = tid & 15, ty = tid >> 4;
  float acc[4][8];
  #pragma unroll
  for (int u = 0; u < 4; u++)
    #pragma unroll
    for (int w = 0; w < 8; w++) acc[u][w] = 0.f;
  for (int kc = 0; kc < HD; kc += 32) {
    #pragma unroll
    for (int l = tid; l < 64 * 32; l += 256) {
      int k = l & 31, m = l >> 5;
      As[k][m] = g_xg[(m0 + m) * HD + kc + k];
    }
    #pragma unroll
    for (int l = tid; l < 32 * 128; l += 256) {
      int k = l >> 7, j = l & 127;
      Bs[k][j] = g_U[(kc + k) * N + j0 + j];
    }
    __syncthreads();
    #pragma unroll
    for (int kk = 0; kk < 32; kk++) {
      float ra[4], rb[8];
      #pragma unroll
      for (int u = 0; u < 4; u++) ra[u] = As[kk][u * 16 + ty];
      #pragma unroll
      for (int w = 0; w < 8; w++) rb[w] = Bs[kk][w * 16 + tx];
      #pragma unroll
      for (int u = 0; u < 4; u++)
        #pragma unroll
        for (int w = 0; w < 8; w++) acc[u][w] += ra[u] * rb[w];
    }
    __syncthreads();
  }
  #pragma unroll
  for (int u = 0; u < 4; u++)
    #pragma unroll
    for (int w = 0; w < 8; w++)
      g_H2[(m0 + u * 16 + ty) * N + j0 + w * 16 + tx] =
          acc[u][w] + g_c2[j0 + w * 16 + tx];
}

// ---------------- K5a/b/c: CSR construction ----------------
__global__ void k_count(const int* __restrict__ ei) {
  int idx = blockIdx.x * blockDim.x + threadIdx.x;
  if (idx >= E2) return;
  int t;
  if (idx < EE) { t = ei[EE + idx]; atomicAdd(&g_cntS[ei[idx]], 1); }
  else t = idx - EE;
  atomicAdd(&g_cntT[t], 1);
}

__global__ void k_scan() {
  __shared__ int part[512];
  int tid = threadIdx.x;
  int b = tid * 3;
  {
    int a0 = g_cntT[b], a1 = g_cntT[b + 1], a2 = g_cntT[b + 2];
    int s = a0 + a1 + a2;
    part[tid] = s;
    __syncthreads();
    for (int o = 1; o < 512; o <<= 1) {
      int v = (tid >= o) ? part[tid - o] : 0;
      __syncthreads();
      part[tid] += v;
      __syncthreads();
    }
    int excl = part[tid] - s;
    g_offT[b] = excl;         g_curT[b] = excl;
    g_offT[b + 1] = excl + a0; g_curT[b + 1] = excl + a0;
    g_offT[b + 2] = excl + a0 + a1; g_curT[b + 2] = excl + a0 + a1;
    if (tid == 511) g_offT[N] = part[511];
    __syncthreads();
  }
  {
    int a0 = g_cntS[b], a1 = g_cntS[b + 1], a2 = g_cntS[b + 2];
    int s = a0 + a1 + a2;
    part[tid] = s;
    __syncthreads();
    for (int o = 1; o < 512; o <<= 1) {
      int v = (tid >= o) ? part[tid - o] : 0;
      __syncthreads();
      part[tid] += v;
      __syncthreads();
    }
    int excl = part[tid] - s;
    g_offS[b] = excl;         g_curS[b] = excl;
    g_offS[b + 1] = excl + a0; g_curS[b + 1] = excl + a0;
    g_offS[b + 2] = excl + a0 + a1; g_curS[b + 2] = excl + a0 + a1;
    if (tid == 511) g_offS[N] = part[511];
  }
}

__global__ void k_fill(const int* __restrict__ ei) {
  int idx = blockIdx.x * blockDim.x + threadIdx.x;
  if (idx >= E2) return;
  int s, t;
  if (idx < EE) { s = ei[idx]; t = ei[EE + idx]; }
  else { s = t = idx - EE; }
  int pos = atomicAdd(&g_curT[t], 1);
  g_srcT[pos] = s;
  if (idx < EE) {
    int ps = atomicAdd(&g_curS[s], 1);
    g_tgtS[ps] = t;
  }
}

// ---------------- K6: fused GAT-1 softmax + xg = P@x (block per target) -----
__global__ __launch_bounds__(128) void k_xg(const float* __restrict__ x) {
  int t = blockIdx.x, tid = threadIdx.x;
  __shared__ int   ss[256];
  __shared__ float sw[256];
  __shared__ float sh[4];
  int p0 = g_offT[t], p1 = g_offT[t + 1];
  float dt = g_da[t];
  // pass 1: segment max
  float m = -3.4e38f;
  for (int p = p0 + tid; p < p1; p += 128)
    m = fmaxf(m, lrelu(g_sa[g_srcT[p]] + dt));
  #pragma unroll
  for (int o = 16; o; o >>= 1) m = fmaxf(m, __shfl_xor_sync(0xFFFFFFFFu, m, o));
  if ((tid & 31) == 0) sh[tid >> 5] = m;
  __syncthreads();
  m = fmaxf(fmaxf(sh[0], sh[1]), fmaxf(sh[2], sh[3]));
  // chunked pass 2: weights + weighted feature accumulation
  float acc = 0.f, dsum = 0.f;
  for (int base = p0; base < p1; base += 256) {
    int nc = min(256, p1 - base);
    for (int q = tid; q < nc; q += 128) {
      int s = g_srcT[base + q];
      float w = expf(lrelu(g_sa[s] + dt) - m);
      ss[q] = s;
      sw[q] = w;
      dsum += w;
    }
    __syncthreads();
    for (int q = 0; q < nc; q++)
      acc += sw[q] * x[ss[q] * HD + tid];
    __syncthreads();
  }
  // block-reduce den
  float den = dsum;
  #pragma unroll
  for (int o = 16; o; o >>= 1) den += __shfl_xor_sync(0xFFFFFFFFu, den, o);
  if ((tid & 31) == 0) sh[tid >> 5] = den;
  __syncthreads();
  den = sh[0] + sh[1] + sh[2] + sh[3];
  g_xg[t * HD + tid] = acc / den;
}

// ---------------- K8: reachability masks ----------------
__global__ void k_B(const int* __restrict__ ei) {
  int e = blockIdx.x * blockDim.x + threadIdx.x;
  if (e >= EE) return;
  int s = ei[e], t = ei[EE + e];
  atomicOr(&g_B[t * NW + (s >> 5)], 1u << (s & 31));
}

__global__ void k_Mb() {
  int i = blockIdx.x;
  __shared__ unsigned m1[NW];
  __shared__ int klist[N];
  __shared__ unsigned part[8][NW];
  __shared__ int nk;
  int cx = threadIdx.x;      // 0..47 column
  int sy = threadIdx.y;      // 0..7 slice
  if (sy == 0) {
    if (cx == 0) nk = 0;
    unsigned w = g_B[i * NW + cx];
    if (cx == (i >> 5)) w |= 1u << (i & 31);
    m1[cx] = w;
  }
  __syncthreads();
  if (sy == 0) {
    unsigned w = m1[cx];
    while (w) {
      int b = __ffs(w) - 1;
      w &= w - 1;
      klist[atomicAdd(&nk, 1)] = cx * 32 + b;
    }
  }
  __syncthreads();
  int n = nk;
  unsigned acc = 0u;
  for (int q = sy; q < n; q += 8) acc |= g_B[klist[q] * NW + cx];
  part[sy][cx] = acc;
  __syncthreads();
  if (sy == 0) {
    unsigned r = m1[cx];
    #pragma unroll
    for (int s = 0; s < 8; s++) r |= part[s][cx];
    g_Mb[i * NW + cx] = r;
  }
}

// ---------------- K9: per-row attention + top-k + output ----------------
__global__ __launch_bounds__(256) void k_row(const float* __restrict__ pas2,
                                             const float* __restrict__ pad2,
                                             const float* __restrict__ pb2,
                                             float* __restrict__ out, int wk) {
  int i = blockIdx.x, tid = threadIdx.x;
  __shared__ float v[N];
  __shared__ unsigned m2[N];
  __shared__ float den[N];
  __shared__ float num[N];
  __shared__ int vlist[N];
  __shared__ unsigned mb[NW];
  __shared__ int nv;
  float as2 = pas2[0], ad2 = pad2[0], b2 = pb2[0];
  if (tid == 0) nv = 0;
  if (tid < NW) mb[tid] = g_Mb[i * NW + tid];
  for (int j = tid; j < N; j += 256) {
    v[j] = g_H2[i * N + j];
    m2[j] = ENC_NEG_INF;
    den[j] = 0.f;
    num[j] = 0.f;
    out[i * N + j] = 0.f;
  }
  if (wk)
    for (int j = tid; j < N; j += 256) out[N * N + i * N + j] = 0.f;
  __syncthreads();
  // collect valid nodes
  for (int w = tid; w < NW; w += 256) {
    unsigned b = mb[w];
    while (b) {
      int t = __ffs(b) - 1;
      b &= b - 1;
      vlist[atomicAdd(&nv, 1)] = w * 32 + t;
    }
  }
  __syncthreads();
  int nvv = nv;
  // pass A: per-target max over valid edges
  for (int li = tid; li < nvv; li += 256) {
    int k = vlist[li];
    float vk = v[k];
    atomicMax(&m2[k], fenc(lrelu((as2 + ad2) * vk)));
    int p0 = g_offS[k], p1 = g_offS[k + 1];
    for (int p = p0; p < p1; p++) {
      int t = g_tgtS[p];
      if ((mb[t >> 5] >> (t & 31)) & 1u) {
        float e = lrelu(as2 * vk + ad2 * v[t]);
        atomicMax(&m2[t], fenc(e));
      }
    }
  }
  __syncthreads();
  // pass B: exp-sum and weighted sum
  for (int li = tid; li < nvv; li += 256) {
    int k = vlist[li];
    float vk = v[k];
    {
      float e = lrelu((as2 + ad2) * vk);
      float w = expf(e - fdec(m2[k]));
      atomicAdd(&den[k], w);
      atomicAdd(&num[k], w * vk);
    }
    int p0 = g_offS[k], p1 = g_offS[k + 1];
    for (int p = p0; p < p1; p++) {
      int t = g_tgtS[p];
      if ((mb[t >> 5] >> (t & 31)) & 1u) {
        float e = lrelu(as2 * vk + ad2 * v[t]);
        float w = expf(e - fdec(m2[t]));
        atomicAdd(&den[t], w);
        atomicAdd(&num[t], w * vk);
      }
    }
  }
  __syncthreads();
  // scores (reuse v)
  for (int li = tid; li < nvv; li += 256) {
    int j = vlist[li];
    v[j] = num[j] / fmaxf(den[j], 1e-12f) + b2;
  }
  __syncthreads();
  // exact rank with stable tie-break by index, then write kept entries
  int kk = (nvv + 1) >> 1;  // ceil(0.5*size)
  for (int li = tid; li < nvv; li += 256) {
    int j = vlist[li];
    float sj = v[j];
    int cnt = 0;
    for (int p = 0; p < nvv; p++) {
      int j2 = vlist[p];
      float s2 = v[j2];
      cnt += (s2 > sj) || ((s2 == sj) && (j2 < j));
    }
    if (cnt < kk) {
      out[i * N + j] = 1.f / (1.f + expf(-sj));
      if (wk) out[N * N + i * N + j] = 1.f;
    }
  }
}

// ---------------- launch ----------------
extern "C" void kernel_launch(void* const* d_in, const int* in_sizes, int n_in,
                              void* d_out, int out_size) {
  const float* x   = (const float*)d_in[0];
  const float* xo  = (const float*)d_in[1];
  const int*   ei  = (const int*)d_in[2];
  const float* W1  = (const float*)d_in[4];
  const float* a1  = (const float*)d_in[5];
  const float* a2  = (const float*)d_in[6];
  const float* b1  = (const float*)d_in[7];
  const float* w2  = (const float*)d_in[8];
  const float* as2 = (const float*)d_in[9];
  const float* ad2 = (const float*)d_in[10];
  const float* b2  = (const float*)d_in[11];
  float* out = (float*)d_out;
  int wk = (out_size >= 2 * N * N) ? 1 : 0;

  k_zero<<<256, 256>>>();
  k_vec1<<<HD + N, 256>>>(W1, a1, a2, b1, w2, xo);
  k_sada<<<(N * 32) / 128, 128>>>(x);
  k_U<<<dim3(12, 2, 10), 256>>>(W1, w2, xo);
  k_count<<<(E2 + 255) / 256, 256>>>(ei);
  k_scan<<<1, 512>>>();
  k_fill<<<(E2 + 255) / 256, 256>>>(ei);
  k_xg<<<N, 128>>>(x);
  k_H2g<<<dim3(12, 24), 256>>>();
  k_B<<<(EE + 255) / 256, 256>>>(ei);
  k_Mb<<<N, dim3(48, 8)>>>();
  k_row<<<N, 256>>>(as2, ad2, b2, out, wk);
}

// round 4
// speedup vs baseline: 1.2579x; 1.0886x over previous
#include <cuda_runtime.h>
#include <math.h>

#define N 1536
#define EE 24576
#define E2 (EE + N)
#define HD 128
#define DD 1280
#define NW 48   // N/32 bitmask words per row

// ---------------- device scratch (no allocations allowed) ----------------
__device__ float g_wa[HD], g_wb[HD], g_c2[N];
__device__ float g_sa[N], g_da[N];
__device__ float g_U[HD * N];          // (128,1536)
__device__ float g_xg[N * HD];         // P @ x  (GAT-1 aggregated features)
__device__ float g_H2[N * N];          // xg @ U + c2  (9.4 MB)
__device__ int   g_cntT[N], g_offT[N + 1], g_curT[N];
__device__ int   g_cntS[N], g_offS[N + 1], g_curS[N];
__device__ int   g_srcT[E2];           // CSR by target (incl self loops)
__device__ int   g_tgtS[EE];           // CSR by source (original edges)
__device__ unsigned g_B[N * NW];       // B[t] = {s : edge s->t}

__device__ __forceinline__ float lrelu(float v) { return v > 0.f ? v : 0.2f * v; }
// order-preserving float<->uint encode for atomicMax on shared memory
__device__ __forceinline__ unsigned fenc(float f) {
  unsigned u = __float_as_uint(f);
  return (u & 0x80000000u) ? ~u : (u | 0x80000000u);
}
__device__ __forceinline__ float fdec(unsigned u) {
  return (u & 0x80000000u) ? __uint_as_float(u & 0x7FFFFFFFu) : __uint_as_float(~u);
}
#define ENC_NEG_INF 0x007FFFFFu  // fenc(-inf-ish)

__device__ __forceinline__ float blockSum(float v, float* sh) {
  __syncthreads();
  #pragma unroll
  for (int o = 16; o; o >>= 1) v += __shfl_xor_sync(0xFFFFFFFFu, v, o);
  if ((threadIdx.x & 31) == 0) sh[threadIdx.x >> 5] = v;
  __syncthreads();
  if (threadIdx.x < 32) {
    v = (threadIdx.x < (blockDim.x >> 5)) ? sh[threadIdx.x] : 0.f;
    #pragma unroll
    for (int o = 4; o; o >>= 1) v += __shfl_xor_sync(0xFFFFFFFFu, v, o);
  }
  return v;
}

// ---------------- K0: zero scratch that is accumulated into ----------------
__global__ void k_zero() {
  int i = blockIdx.x * blockDim.x + threadIdx.x;
  int stride = gridDim.x * blockDim.x;
  for (int p = i; p < HD * N; p += stride) g_U[p] = 0.f;
  for (int p = i; p < N * NW; p += stride) g_B[p] = 0u;
  for (int p = i; p < N; p += stride) { g_cntT[p] = 0; g_cntS[p] = 0; }
}

// ---------------- K1: wa = W1@a_src1, wb = W1@a_dst1, c2[j] = sum b1*w2*xo ----
__global__ void k_vec1(const float* __restrict__ W1, const float* __restrict__ a1,
                       const float* __restrict__ a2, const float* __restrict__ b1,
                       const float* __restrict__ w2, const float* __restrict__ xo) {
  __shared__ float sh[8];
  int b = blockIdx.x, tid = threadIdx.x;
  if (b < HD) {
    float s1 = 0.f, s2 = 0.f;
    for (int d = tid; d < DD; d += 256) {
      float w = W1[b * DD + d];
      s1 += w * a1[d]; s2 += w * a2[d];
    }
    float r1 = blockSum(s1, sh);
    float r2 = blockSum(s2, sh);
    if (tid == 0) { g_wa[b] = r1; g_wb[b] = r2; }
  } else {
    int j = b - HD;
    float s = 0.f;
    for (int d = tid; d < DD; d += 256) s += b1[d] * w2[d] * xo[j * DD + d];
    float r = blockSum(s, sh);
    if (tid == 0) g_c2[j] = r;
  }
}

// ---------------- K2: sa = x@wa, da = x@wb (warp per node) ----------------
__global__ void k_sada(const float* __restrict__ x) {
  int w = (blockIdx.x * blockDim.x + threadIdx.x) >> 5;
  int lane = threadIdx.x & 31;
  if (w >= N) return;
  float s1 = 0.f, s2 = 0.f;
  #pragma unroll
  for (int k = lane; k < HD; k += 32) {
    float xv = x[w * HD + k];
    s1 += xv * g_wa[k]; s2 += xv * g_wb[k];
  }
  #pragma unroll
  for (int o = 16; o; o >>= 1) {
    s1 += __shfl_xor_sync(0xFFFFFFFFu, s1, o);
    s2 += __shfl_xor_sync(0xFFFFFFFFu, s2, o);
  }
  if (lane == 0) { g_sa[w] = s1; g_da[w] = s2; }
}

// ---- K3: U = (W1 .* w2) @ xo^T  (64x128 tiles, split-K, double-buffered) ----
__global__ __launch_bounds__(256, 2) void k_U(const float* __restrict__ W1,
                                              const float* __restrict__ w2,
                                              const float* __restrict__ xo) {
  __shared__ float As[2][16][65];    // [buf][k][m]
  __shared__ float Bs[2][16][129];   // [buf][k][j]
  int j0 = blockIdx.x * 128;
  int m0 = blockIdx.y * 64;
  int k0 = blockIdx.z * 128;
  int tid = threadIdx.x, tx = tid & 15, ty = tid >> 4;
  float acc[4][8];
  #pragma unroll
  for (int u = 0; u < 4; u++)
    #pragma unroll
    for (int w = 0; w < 8; w++) acc[u][w] = 0.f;

  auto load = [&](int buf, int kc) {
    #pragma unroll
    for (int l = tid; l < 64 * 16; l += 256) {
      int k = l & 15, m = l >> 4;
      As[buf][k][m] = W1[(m0 + m) * DD + k0 + kc + k] * w2[k0 + kc + k];
    }
    #pragma unroll
    for (int l = tid; l < 128 * 16; l += 256) {
      int k = l & 15, j = l >> 4;
      Bs[buf][k][j] = xo[(j0 + j) * DD + k0 + kc + k];
    }
  };
  load(0, 0);
  __syncthreads();
  for (int c = 0; c < 8; c++) {
    int buf = c & 1;
    if (c < 7) load(buf ^ 1, (c + 1) * 16);
    #pragma unroll
    for (int kk = 0; kk < 16; kk++) {
      float ra[4], rb[8];
      #pragma unroll
      for (int u = 0; u < 4; u++) ra[u] = As[buf][kk][u * 16 + ty];
      #pragma unroll
      for (int w = 0; w < 8; w++) rb[w] = Bs[buf][kk][w * 16 + tx];
      #pragma unroll
      for (int u = 0; u < 4; u++)
        #pragma unroll
        for (int w = 0; w < 8; w++) acc[u][w] += ra[u] * rb[w];
    }
    __syncthreads();
  }
  #pragma unroll
  for (int u = 0; u < 4; u++)
    #pragma unroll
    for (int w = 0; w < 8; w++)
      atomicAdd(&g_U[(m0 + u * 16 + ty) * N + j0 + w * 16 + tx], acc[u][w]);
}

// ---------------- K4: H2 = xg @ U + c2 (64x128 tiles, double-buffered) ------
__global__ __launch_bounds__(256, 2) void k_H2g() {
  __shared__ float As[2][16][65];    // [buf][k][m]
  __shared__ float Bs[2][16][129];   // [buf][k][j]
  int j0 = blockIdx.x * 128;
  int m0 = blockIdx.y * 64;
  int tid = threadIdx.x, tx = tid & 15, ty = tid >> 4;
  float acc[4][8];
  #pragma unroll
  for (int u = 0; u < 4; u++)
    #pragma unroll
    for (int w = 0; w < 8; w++) acc[u][w] = 0.f;

  auto load = [&](int buf, int kc) {
    #pragma unroll
    for (int l = tid; l < 64 * 16; l += 256) {
      int k = l & 15, m = l >> 4;
      As[buf][k][m] = g_xg[(m0 + m) * HD + kc + k];
    }
    #pragma unroll
    for (int l = tid; l < 16 * 128; l += 256) {
      int j = l & 127, k = l >> 7;
      Bs[buf][k][j] = g_U[(kc + k) * N + j0 + j];
    }
  };
  load(0, 0);
  __syncthreads();
  for (int c = 0; c < 8; c++) {
    int buf = c & 1;
    if (c < 7) load(buf ^ 1, (c + 1) * 16);
    #pragma unroll
    for (int kk = 0; kk < 16; kk++) {
      float ra[4], rb[8];
      #pragma unroll
      for (int u = 0; u < 4; u++) ra[u] = As[buf][kk][u * 16 + ty];
      #pragma unroll
      for (int w = 0; w < 8; w++) rb[w] = Bs[buf][kk][w * 16 + tx];
      #pragma unroll
      for (int u = 0; u < 4; u++)
        #pragma unroll
        for (int w = 0; w < 8; w++) acc[u][w] += ra[u] * rb[w];
    }
    __syncthreads();
  }
  #pragma unroll
  for (int u = 0; u < 4; u++)
    #pragma unroll
    for (int w = 0; w < 8; w++)
      g_H2[(m0 + u * 16 + ty) * N + j0 + w * 16 + tx] =
          acc[u][w] + g_c2[j0 + w * 16 + tx];
}

// ---------------- K5a: fused degree count + in-mask build ----------------
__global__ void k_edges(const int* __restrict__ ei) {
  int idx = blockIdx.x * blockDim.x + threadIdx.x;
  if (idx >= E2) return;
  if (idx < EE) {
    int s = ei[idx], t = ei[EE + idx];
    atomicAdd(&g_cntS[s], 1);
    atomicAdd(&g_cntT[t], 1);
    atomicOr(&g_B[t * NW + (s >> 5)], 1u << (s & 31));
  } else {
    int t = idx - EE;
    atomicAdd(&g_cntT[t], 1);
  }
}

// ---------------- K5b: exclusive scans ----------------
__global__ void k_scan() {
  __shared__ int part[512];
  int tid = threadIdx.x;
  int b = tid * 3;
  {
    int a0 = g_cntT[b], a1 = g_cntT[b + 1], a2 = g_cntT[b + 2];
    int s = a0 + a1 + a2;
    part[tid] = s;
    __syncthreads();
    for (int o = 1; o < 512; o <<= 1) {
      int v = (tid >= o) ? part[tid - o] : 0;
      __syncthreads();
      part[tid] += v;
      __syncthreads();
    }
    int excl = part[tid] - s;
    g_offT[b] = excl;              g_curT[b] = excl;
    g_offT[b + 1] = excl + a0;     g_curT[b + 1] = excl + a0;
    g_offT[b + 2] = excl + a0 + a1; g_curT[b + 2] = excl + a0 + a1;
    if (tid == 511) g_offT[N] = part[511];
    __syncthreads();
  }
  {
    int a0 = g_cntS[b], a1 = g_cntS[b + 1], a2 = g_cntS[b + 2];
    int s = a0 + a1 + a2;
    part[tid] = s;
    __syncthreads();
    for (int o = 1; o < 512; o <<= 1) {
      int v = (tid >= o) ? part[tid - o] : 0;
      __syncthreads();
      part[tid] += v;
      __syncthreads();
    }
    int excl = part[tid] - s;
    g_offS[b] = excl;              g_curS[b] = excl;
    g_offS[b + 1] = excl + a0;     g_curS[b + 1] = excl + a0;
    g_offS[b + 2] = excl + a0 + a1; g_curS[b + 2] = excl + a0 + a1;
    if (tid == 511) g_offS[N] = part[511];
  }
}

// ---------------- K5c: CSR fill ----------------
__global__ void k_fill(const int* __restrict__ ei) {
  int idx = blockIdx.x * blockDim.x + threadIdx.x;
  if (idx >= E2) return;
  int s, t;
  if (idx < EE) { s = ei[idx]; t = ei[EE + idx]; }
  else { s = t = idx - EE; }
  int pos = atomicAdd(&g_curT[t], 1);
  g_srcT[pos] = s;
  if (idx < EE) {
    int ps = atomicAdd(&g_curS[s], 1);
    g_tgtS[ps] = t;
  }
}

// ---------------- K6: fused GAT-1 softmax + xg = P@x (block per target) -----
__global__ __launch_bounds__(128) void k_xg(const float* __restrict__ x) {
  int t = blockIdx.x, tid = threadIdx.x;
  __shared__ int   ss[256];
  __shared__ float sw[256];
  __shared__ float sh[4];
  int p0 = g_offT[t], p1 = g_offT[t + 1];
  float dt = g_da[t];
  float m = -3.4e38f;
  for (int p = p0 + tid; p < p1; p += 128)
    m = fmaxf(m, lrelu(g_sa[g_srcT[p]] + dt));
  #pragma unroll
  for (int o = 16; o; o >>= 1) m = fmaxf(m, __shfl_xor_sync(0xFFFFFFFFu, m, o));
  if ((tid & 31) == 0) sh[tid >> 5] = m;
  __syncthreads();
  m = fmaxf(fmaxf(sh[0], sh[1]), fmaxf(sh[2], sh[3]));
  float acc = 0.f, dsum = 0.f;
  for (int base = p0; base < p1; base += 256) {
    int nc = min(256, p1 - base);
    for (int q = tid; q < nc; q += 128) {
      int s = g_srcT[base + q];
      float w = expf(lrelu(g_sa[s] + dt) - m);
      ss[q] = s;
      sw[q] = w;
      dsum += w;
    }
    __syncthreads();
    for (int q = 0; q < nc; q++)
      acc += sw[q] * x[ss[q] * HD + tid];
    __syncthreads();
  }
  float den = dsum;
  #pragma unroll
  for (int o = 16; o; o >>= 1) den += __shfl_xor_sync(0xFFFFFFFFu, den, o);
  if ((tid & 31) == 0) sh[tid >> 5] = den;
  __syncthreads();
  den = sh[0] + sh[1] + sh[2] + sh[3];
  g_xg[t * HD + tid] = acc / den;
}

// ------- K9: per-row 2-hop mask + attention + bitonic top-k + output -------
__global__ __launch_bounds__(256) void k_row(const float* __restrict__ pas2,
                                             const float* __restrict__ pad2,
                                             const float* __restrict__ pb2,
                                             float* __restrict__ out, int wk) {
  int i = blockIdx.x, tid = threadIdx.x;
  __shared__ float v[N];
  __shared__ int vlist[N];
  __shared__ __align__(16) char pool[18432];   // m2 | den | num, later keys
  __shared__ unsigned mb[NW];
  __shared__ int wcnt[NW + 1];
  unsigned* m2 = (unsigned*)pool;
  float* den = (float*)(pool + 6144);
  float* num = (float*)(pool + 12288);
  unsigned long long* keys = (unsigned long long*)pool;

  float as2 = pas2[0], ad2 = pad2[0], b2 = pb2[0];

  if (tid < NW) {
    unsigned w = g_B[i * NW + tid];
    if (tid == (i >> 5)) w |= 1u << (i & 31);
    mb[tid] = w;
  }
  for (int j = tid; j < N; j += 256) {
    v[j] = g_H2[i * N + j];
    m2[j] = ENC_NEG_INF;
    den[j] = 0.f;
    num[j] = 0.f;
    out[i * N + j] = 0.f;
    if (wk) out[N * N + i * N + j] = 0.f;
  }
  __syncthreads();
  // 1-hop list into vlist (prefix by word popcounts)
  if (tid < NW) wcnt[tid] = __popc(mb[tid]);
  __syncthreads();
  if (tid == 0) {
    int s = 0;
    for (int w = 0; w < NW; w++) { int c = wcnt[w]; wcnt[w] = s; s += c; }
    wcnt[NW] = s;
  }
  __syncthreads();
  int nk = wcnt[NW];
  if (tid < NW) {
    unsigned b = mb[tid]; int o = wcnt[tid];
    while (b) { int t = __ffs(b) - 1; b &= b - 1; vlist[o++] = tid * 32 + t; }
  }
  __syncthreads();
  // 2-hop: OR in-masks of 1-hop nodes
  if (tid < 4 * NW) {
    int sy = tid / NW, cx = tid % NW;
    unsigned acc = 0u;
    for (int q = sy; q < nk; q += 4) acc |= g_B[vlist[q] * NW + cx];
    atomicOr(&mb[cx], acc);
  }
  __syncthreads();
  // valid list from mb
  if (tid < NW) wcnt[tid] = __popc(mb[tid]);
  __syncthreads();
  if (tid == 0) {
    int s = 0;
    for (int w = 0; w < NW; w++) { int c = wcnt[w]; wcnt[w] = s; s += c; }
    wcnt[NW] = s;
  }
  __syncthreads();
  int nvv = wcnt[NW];
  if (tid < NW) {
    unsigned b = mb[tid]; int o = wcnt[tid];
    while (b) { int t = __ffs(b) - 1; b &= b - 1; vlist[o++] = tid * 32 + t; }
  }
  __syncthreads();
  // pass A: per-target max over valid edges (self-loops + out-edges of valid k)
  for (int li = tid; li < nvv; li += 256) {
    int k = vlist[li];
    float vk = v[k];
    atomicMax(&m2[k], fenc(lrelu((as2 + ad2) * vk)));
    int p0 = g_offS[k], p1 = g_offS[k + 1];
    for (int p = p0; p < p1; p++) {
      int t = g_tgtS[p];
      if ((mb[t >> 5] >> (t & 31)) & 1u)
        atomicMax(&m2[t], fenc(lrelu(as2 * vk + ad2 * v[t])));
    }
  }
  __syncthreads();
  // pass B: exp-sum and weighted sum
  for (int li = tid; li < nvv; li += 256) {
    int k = vlist[li];
    float vk = v[k];
    {
      float w = expf(lrelu((as2 + ad2) * vk) - fdec(m2[k]));
      atomicAdd(&den[k], w);
      atomicAdd(&num[k], w * vk);
    }
    int p0 = g_offS[k], p1 = g_offS[k + 1];
    for (int p = p0; p < p1; p++) {
      int t = g_tgtS[p];
      if ((mb[t >> 5] >> (t & 31)) & 1u) {
        float w = expf(lrelu(as2 * vk + ad2 * v[t]) - fdec(m2[t]));
        atomicAdd(&den[t], w);
        atomicAdd(&num[t], w * vk);
      }
    }
  }
  __syncthreads();
  // scores (reuse v)
  for (int li = tid; li < nvv; li += 256) {
    int j = vlist[li];
    v[j] = num[j] / fmaxf(den[j], 1e-12f) + b2;
  }
  __syncthreads();
  // pack 64-bit keys (score desc, idx asc on ties) — overwrites m2/den/num
  int MPAD = 2;
  while (MPAD < nvv) MPAD <<= 1;
  for (int li = tid; li < MPAD; li += 256) {
    if (li < nvv) {
      int j = vlist[li];
      keys[li] = ((unsigned long long)fenc(v[j]) << 32) | (unsigned)(~j);
    } else keys[li] = 0ull;
  }
  __syncthreads();
  // bitonic sort descending
  for (int ks = 2; ks <= MPAD; ks <<= 1) {
    for (int jj = ks >> 1; jj > 0; jj >>= 1) {
      for (int idx = tid; idx < MPAD; idx += 256) {
        int l = idx ^ jj;
        if (l > idx) {
          unsigned long long a = keys[idx], b = keys[l];
          if (((idx & ks) == 0) ? (a < b) : (a > b)) {
            keys[idx] = b;
            keys[l] = a;
          }
        }
      }
      __syncthreads();
    }
  }
  // first kk sorted entries are kept
  int kk = (nvv + 1) >> 1;
  for (int p = tid; p < kk; p += 256) {
    int j = (int)(~(unsigned)(keys[p] & 0xFFFFFFFFull));
    float sj = v[j];
    out[i * N + j] = 1.f / (1.f + expf(-sj));
    if (wk) out[N * N + i * N + j] = 1.f;
  }
}

// ---------------- launch ----------------
extern "C" void kernel_launch(void* const* d_in, const int* in_sizes, int n_in,
                              void* d_out, int out_size) {
  const float* x   = (const float*)d_in[0];
  const float* xo  = (const float*)d_in[1];
  const int*   ei  = (const int*)d_in[2];
  const float* W1  = (const float*)d_in[4];
  const float* a1  = (const float*)d_in[5];
  const float* a2  = (const float*)d_in[6];
  const float* b1  = (const float*)d_in[7];
  const float* w2  = (const float*)d_in[8];
  const float* as2 = (const float*)d_in[9];
  const float* ad2 = (const float*)d_in[10];
  const float* b2  = (const float*)d_in[11];
  float* out = (float*)d_out;
  int wk = (out_size >= 2 * N * N) ? 1 : 0;

  k_zero<<<256, 256>>>();
  k_vec1<<<HD + N, 256>>>(W1, a1, a2, b1, w2, xo);
  k_sada<<<(N * 32) / 128, 128>>>(x);
  k_U<<<dim3(12, 2, 10), 256>>>(W1, w2, xo);
  k_edges<<<(E2 + 255) / 256, 256>>>(ei);
  k_scan<<<1, 512>>>();
  k_fill<<<(E2 + 255) / 256, 256>>>(ei);
  k_xg<<<N, 128>>>(x);
  k_H2g<<<dim3(12, 24), 256>>>();
  k_row<<<N, 256>>>(as2, ad2, b2, out, wk);
}

// round 5
// speedup vs baseline: 1.2684x; 1.0084x over previous
#include <cuda_runtime.h>
#include <math.h>

#define N 1536
#define EE 24576
#define E2 (EE + N)
#define HD 128
#define DD 1280
#define NW 48   // N/32 bitmask words per row

// ---------------- device scratch (no allocations allowed) ----------------
// Invariant: g_U, g_B, g_cntT, g_cntS are ZERO at entry to kernel_launch.
// (CUDA zero-inits them at module load; each execution re-zeros them at its
//  tail: g_U in k_row, g_cnt in k_fill, g_B in k_clean.)
__device__ float g_wa[HD], g_wb[HD], g_c2[N];
__device__ float g_sa[N], g_da[N];
__device__ float g_U[HD * N];          // (128,1536)
__device__ float g_xg[N * HD];         // P @ x  (GAT-1 aggregated features)
__device__ float g_H2[N * N];          // xg @ U + c2  (9.4 MB)
__device__ int   g_cntT[N], g_offT[N + 1], g_curT[N];
__device__ int   g_cntS[N], g_offS[N + 1], g_curS[N];
__device__ int   g_srcT[E2];           // CSR by target (incl self loops)
__device__ int   g_tgtS[EE];           // CSR by source (original edges)
__device__ unsigned g_B[N * NW];       // B[t] = {s : edge s->t}

__device__ __forceinline__ float lrelu(float v) { return v > 0.f ? v : 0.2f * v; }
__device__ __forceinline__ unsigned fenc(float f) {
  unsigned u = __float_as_uint(f);
  return (u & 0x80000000u) ? ~u : (u | 0x80000000u);
}
__device__ __forceinline__ float fdec(unsigned u) {
  return (u & 0x80000000u) ? __uint_as_float(u & 0x7FFFFFFFu) : __uint_as_float(~u);
}
#define ENC_NEG_INF 0x007FFFFFu

__device__ __forceinline__ float blockSum256(float v, float* sh) {
  __syncthreads();
  #pragma unroll
  for (int o = 16; o; o >>= 1) v += __shfl_xor_sync(0xFFFFFFFFu, v, o);
  if ((threadIdx.x & 31) == 0) sh[threadIdx.x >> 5] = v;
  __syncthreads();
  if (threadIdx.x < 32) {
    v = (threadIdx.x < 8) ? sh[threadIdx.x] : 0.f;
    #pragma unroll
    for (int o = 4; o; o >>= 1) v += __shfl_xor_sync(0xFFFFFFFFu, v, o);
  }
  return v;
}

// ============ kA: vec1 (blocks 0..1663) + edge count/mask (1664..1765) ======
__global__ __launch_bounds__(256) void kA(const float* __restrict__ W1,
                                          const float* __restrict__ a1,
                                          const float* __restrict__ a2,
                                          const float* __restrict__ b1,
                                          const float* __restrict__ w2,
                                          const float* __restrict__ xo,
                                          const int* __restrict__ ei) {
  __shared__ float sh[8];
  int b = blockIdx.x, tid = threadIdx.x;
  if (b < HD) {
    float s1 = 0.f, s2 = 0.f;
    for (int d = tid; d < DD; d += 256) {
      float w = W1[b * DD + d];
      s1 += w * a1[d]; s2 += w * a2[d];
    }
    float r1 = blockSum256(s1, sh);
    float r2 = blockSum256(s2, sh);
    if (tid == 0) { g_wa[b] = r1; g_wb[b] = r2; }
  } else if (b < HD + N) {
    int j = b - HD;
    float s = 0.f;
    for (int d = tid; d < DD; d += 256) s += b1[d] * w2[d] * xo[j * DD + d];
    float r = blockSum256(s, sh);
    if (tid == 0) g_c2[j] = r;
  } else {
    int idx = (b - (HD + N)) * 256 + tid;
    if (idx < E2) {
      if (idx < EE) {
        int s = ei[idx], t = ei[EE + idx];
        atomicAdd(&g_cntS[s], 1);
        atomicAdd(&g_cntT[t], 1);
        atomicOr(&g_B[t * NW + (s >> 5)], 1u << (s & 31));
      } else {
        atomicAdd(&g_cntT[idx - EE], 1);
      }
    }
  }
}

// ============ kB: k_U (0..479) + scan (480) + sada (481..672) ==============
__global__ __launch_bounds__(256, 2) void kB(const float* __restrict__ W1,
                                             const float* __restrict__ w2,
                                             const float* __restrict__ xo,
                                             const float* __restrict__ x) {
  int b = blockIdx.x, tid = threadIdx.x;
  if (b < 480) {
    // --- U = (W1 .* w2) @ xo^T, 64x128 tile, K-chunk 64, split-K z=20 ---
    __shared__ float As[2][16][65];
    __shared__ float Bs[2][16][129];
    int j0 = (b % 12) * 128;
    int m0 = ((b / 12) & 1) * 64;
    int k0 = (b / 24) * 64;
    int tx = tid & 15, ty = tid >> 4;
    float acc[4][8];
    #pragma unroll
    for (int u = 0; u < 4; u++)
      #pragma unroll
      for (int w = 0; w < 8; w++) acc[u][w] = 0.f;
    auto load = [&](int buf, int kc) {
      #pragma unroll
      for (int l = tid; l < 64 * 16; l += 256) {
        int k = l & 15, m = l >> 4;
        As[buf][k][m] = W1[(m0 + m) * DD + k0 + kc + k] * w2[k0 + kc + k];
      }
      #pragma unroll
      for (int l = tid; l < 128 * 16; l += 256) {
        int k = l & 15, j = l >> 4;
        Bs[buf][k][j] = xo[(j0 + j) * DD + k0 + kc + k];
      }
    };
    load(0, 0);
    __syncthreads();
    for (int c = 0; c < 4; c++) {
      int buf = c & 1;
      if (c < 3) load(buf ^ 1, (c + 1) * 16);
      #pragma unroll
      for (int kk = 0; kk < 16; kk++) {
        float ra[4], rb[8];
        #pragma unroll
        for (int u = 0; u < 4; u++) ra[u] = As[buf][kk][u * 16 + ty];
        #pragma unroll
        for (int w = 0; w < 8; w++) rb[w] = Bs[buf][kk][w * 16 + tx];
        #pragma unroll
        for (int u = 0; u < 4; u++)
          #pragma unroll
          for (int w = 0; w < 8; w++) acc[u][w] += ra[u] * rb[w];
      }
      __syncthreads();
    }
    #pragma unroll
    for (int u = 0; u < 4; u++)
      #pragma unroll
      for (int w = 0; w < 8; w++)
        atomicAdd(&g_U[(m0 + u * 16 + ty) * N + j0 + w * 16 + tx], acc[u][w]);
  } else if (b == 480) {
    // --- exclusive scans of cntT / cntS (256 threads, 6 nodes each) ---
    __shared__ int part[256];
    int base = tid * 6;
    {
      int a[6]; int s = 0;
      #pragma unroll
      for (int u = 0; u < 6; u++) { a[u] = g_cntT[base + u]; s += a[u]; }
      part[tid] = s;
      __syncthreads();
      for (int o = 1; o < 256; o <<= 1) {
        int v = (tid >= o) ? part[tid - o] : 0;
        __syncthreads();
        part[tid] += v;
        __syncthreads();
      }
      int excl = part[tid] - s;
      #pragma unroll
      for (int u = 0; u < 6; u++) {
        g_offT[base + u] = excl; g_curT[base + u] = excl; excl += a[u];
      }
      if (tid == 255) g_offT[N] = part[255];
      __syncthreads();
    }
    {
      int a[6]; int s = 0;
      #pragma unroll
      for (int u = 0; u < 6; u++) { a[u] = g_cntS[base + u]; s += a[u]; }
      part[tid] = s;
      __syncthreads();
      for (int o = 1; o < 256; o <<= 1) {
        int v = (tid >= o) ? part[tid - o] : 0;
        __syncthreads();
        part[tid] += v;
        __syncthreads();
      }
      int excl = part[tid] - s;
      #pragma unroll
      for (int u = 0; u < 6; u++) {
        g_offS[base + u] = excl; g_curS[base + u] = excl; excl += a[u];
      }
      if (tid == 255) g_offS[N] = part[255];
    }
  } else {
    // --- sada: warp per node ---
    int node = (b - 481) * 8 + (tid >> 5);
    int lane = tid & 31;
    if (node < N) {
      float s1 = 0.f, s2 = 0.f;
      #pragma unroll
      for (int k = lane; k < HD; k += 32) {
        float xv = x[node * HD + k];
        s1 += xv * g_wa[k]; s2 += xv * g_wb[k];
      }
      #pragma unroll
      for (int o = 16; o; o >>= 1) {
        s1 += __shfl_xor_sync(0xFFFFFFFFu, s1, o);
        s2 += __shfl_xor_sync(0xFFFFFFFFu, s2, o);
      }
      if (lane == 0) { g_sa[node] = s1; g_da[node] = s2; }
    }
  }
}

// ============ kC: CSR fill + re-zero cnt arrays ==============
__global__ void kC(const int* __restrict__ ei) {
  int idx = blockIdx.x * blockDim.x + threadIdx.x;
  if (idx < N) { g_cntT[idx] = 0; g_cntS[idx] = 0; }  // restore invariant
  if (idx >= E2) return;
  int s, t;
  if (idx < EE) { s = ei[idx]; t = ei[EE + idx]; }
  else { s = t = idx - EE; }
  int pos = atomicAdd(&g_curT[t], 1);
  g_srcT[pos] = s;
  if (idx < EE) {
    int ps = atomicAdd(&g_curS[s], 1);
    g_tgtS[ps] = t;
  }
}

// ============ kD: fused GAT-1 softmax + xg = P@x (block per target) ========
__global__ __launch_bounds__(128) void kD(const float* __restrict__ x) {
  int t = blockIdx.x, tid = threadIdx.x;
  __shared__ int   ss[256];
  __shared__ float sw[256];
  __shared__ float sh[4];
  int p0 = g_offT[t], p1 = g_offT[t + 1];
  float dt = g_da[t];
  float m = -3.4e38f;
  for (int p = p0 + tid; p < p1; p += 128)
    m = fmaxf(m, lrelu(g_sa[g_srcT[p]] + dt));
  #pragma unroll
  for (int o = 16; o; o >>= 1) m = fmaxf(m, __shfl_xor_sync(0xFFFFFFFFu, m, o));
  if ((tid & 31) == 0) sh[tid >> 5] = m;
  __syncthreads();
  m = fmaxf(fmaxf(sh[0], sh[1]), fmaxf(sh[2], sh[3]));
  float acc = 0.f, dsum = 0.f;
  for (int base = p0; base < p1; base += 256) {
    int nc = min(256, p1 - base);
    for (int q = tid; q < nc; q += 128) {
      int s = g_srcT[base + q];
      float w = expf(lrelu(g_sa[s] + dt) - m);
      ss[q] = s;
      sw[q] = w;
      dsum += w;
    }
    __syncthreads();
    for (int q = 0; q < nc; q++)
      acc += sw[q] * x[ss[q] * HD + tid];
    __syncthreads();
  }
  float den = dsum;
  #pragma unroll
  for (int o = 16; o; o >>= 1) den += __shfl_xor_sync(0xFFFFFFFFu, den, o);
  if ((tid & 31) == 0) sh[tid >> 5] = den;
  __syncthreads();
  den = sh[0] + sh[1] + sh[2] + sh[3];
  g_xg[t * HD + tid] = acc / den;
}

// ============ kE: H2 = xg @ U + c2 (64x64 tiles, 576 CTAs) ==============
__global__ __launch_bounds__(256) void kE() {
  __shared__ float As[2][16][65];
  __shared__ float Bs[2][16][65];
  int b = blockIdx.x;
  int j0 = (b % 24) * 64;
  int m0 = (b / 24) * 64;
  int tid = threadIdx.x, tx = tid & 15, ty = tid >> 4;
  float acc[4][4];
  #pragma unroll
  for (int u = 0; u < 4; u++)
    #pragma unroll
    for (int w = 0; w < 4; w++) acc[u][w] = 0.f;
  auto load = [&](int buf, int kc) {
    #pragma unroll
    for (int l = tid; l < 64 * 16; l += 256) {
      int k = l & 15, m = l >> 4;
      As[buf][k][m] = g_xg[(m0 + m) * HD + kc + k];
    }
    #pragma unroll
    for (int l = tid; l < 16 * 64; l += 256) {
      int j = l & 63, k = l >> 6;
      Bs[buf][k][j] = g_U[(kc + k) * N + j0 + j];
    }
  };
  load(0, 0);
  __syncthreads();
  for (int c = 0; c < 8; c++) {
    int buf = c & 1;
    if (c < 7) load(buf ^ 1, (c + 1) * 16);
    #pragma unroll
    for (int kk = 0; kk < 16; kk++) {
      float ra[4], rb[4];
      #pragma unroll
      for (int u = 0; u < 4; u++) ra[u] = As[buf][kk][u * 16 + ty];
      #pragma unroll
      for (int w = 0; w < 4; w++) rb[w] = Bs[buf][kk][w * 16 + tx];
      #pragma unroll
      for (int u = 0; u < 4; u++)
        #pragma unroll
        for (int w = 0; w < 4; w++) acc[u][w] += ra[u] * rb[w];
    }
    __syncthreads();
  }
  #pragma unroll
  for (int u = 0; u < 4; u++)
    #pragma unroll
    for (int w = 0; w < 4; w++)
      g_H2[(m0 + u * 16 + ty) * N + j0 + w * 16 + tx] =
          acc[u][w] + g_c2[j0 + w * 16 + tx];
}

// ==== kF: per-row 2-hop mask + attention + bitonic top-k + output + U-clean =
__global__ __launch_bounds__(256) void kF(const float* __restrict__ pas2,
                                          const float* __restrict__ pad2,
                                          const float* __restrict__ pb2,
                                          float* __restrict__ out, int wk) {
  int i = blockIdx.x, tid = threadIdx.x;
  // restore invariant: zero g_U (1536 blocks x 128 floats = full array)
  if (tid < 128) g_U[i * 128 + tid] = 0.f;
  __shared__ float v[N];
  __shared__ int vlist[N];
  __shared__ __align__(16) char pool[18432];
  __shared__ unsigned mb[NW];
  __shared__ int wcnt[NW + 1];
  unsigned* m2 = (unsigned*)pool;
  float* den = (float*)(pool + 6144);
  float* num = (float*)(pool + 12288);
  unsigned long long* keys = (unsigned long long*)pool;

  float as2 = pas2[0], ad2 = pad2[0], b2 = pb2[0];

  if (tid < NW) {
    unsigned w = g_B[i * NW + tid];
    if (tid == (i >> 5)) w |= 1u << (i & 31);
    mb[tid] = w;
  }
  for (int j = tid; j < N; j += 256) {
    v[j] = g_H2[i * N + j];
    m2[j] = ENC_NEG_INF;
    den[j] = 0.f;
    num[j] = 0.f;
    out[i * N + j] = 0.f;
    if (wk) out[N * N + i * N + j] = 0.f;
  }
  __syncthreads();
  if (tid < NW) wcnt[tid] = __popc(mb[tid]);
  __syncthreads();
  if (tid == 0) {
    int s = 0;
    for (int w = 0; w < NW; w++) { int c = wcnt[w]; wcnt[w] = s; s += c; }
    wcnt[NW] = s;
  }
  __syncthreads();
  int nk = wcnt[NW];
  if (tid < NW) {
    unsigned b = mb[tid]; int o = wcnt[tid];
    while (b) { int t = __ffs(b) - 1; b &= b - 1; vlist[o++] = tid * 32 + t; }
  }
  __syncthreads();
  if (tid < 4 * NW) {
    int sy = tid / NW, cx = tid % NW;
    unsigned acc = 0u;
    for (int q = sy; q < nk; q += 4) acc |= g_B[vlist[q] * NW + cx];
    atomicOr(&mb[cx], acc);
  }
  __syncthreads();
  if (tid < NW) wcnt[tid] = __popc(mb[tid]);
  __syncthreads();
  if (tid == 0) {
    int s = 0;
    for (int w = 0; w < NW; w++) { int c = wcnt[w]; wcnt[w] = s; s += c; }
    wcnt[NW] = s;
  }
  __syncthreads();
  int nvv = wcnt[NW];
  if (tid < NW) {
    unsigned b = mb[tid]; int o = wcnt[tid];
    while (b) { int t = __ffs(b) - 1; b &= b - 1; vlist[o++] = tid * 32 + t; }
  }
  __syncthreads();
  // pass A: per-target max over valid edges
  for (int li = tid; li < nvv; li += 256) {
    int k = vlist[li];
    float vk = v[k];
    atomicMax(&m2[k], fenc(lrelu((as2 + ad2) * vk)));
    int p0 = g_offS[k], p1 = g_offS[k + 1];
    for (int p = p0; p < p1; p++) {
      int t = g_tgtS[p];
      if ((mb[t >> 5] >> (t & 31)) & 1u)
        atomicMax(&m2[t], fenc(lrelu(as2 * vk + ad2 * v[t])));
    }
  }
  __syncthreads();
  // pass B: exp-sum and weighted sum
  for (int li = tid; li < nvv; li += 256) {
    int k = vlist[li];
    float vk = v[k];
    {
      float w = expf(lrelu((as2 + ad2) * vk) - fdec(m2[k]));
      atomicAdd(&den[k], w);
      atomicAdd(&num[k], w * vk);
    }
    int p0 = g_offS[k], p1 = g_offS[k + 1];
    for (int p = p0; p < p1; p++) {
      int t = g_tgtS[p];
      if ((mb[t >> 5] >> (t & 31)) & 1u) {
        float w = expf(lrelu(as2 * vk + ad2 * v[t]) - fdec(m2[t]));
        atomicAdd(&den[t], w);
        atomicAdd(&num[t], w * vk);
      }
    }
  }
  __syncthreads();
  for (int li = tid; li < nvv; li += 256) {
    int j = vlist[li];
    v[j] = num[j] / fmaxf(den[j], 1e-12f) + b2;
  }
  __syncthreads();
  int MPAD = 2;
  while (MPAD < nvv) MPAD <<= 1;
  for (int li = tid; li < MPAD; li += 256) {
    if (li < nvv) {
      int j = vlist[li];
      keys[li] = ((unsigned long long)fenc(v[j]) << 32) | (unsigned)(~j);
    } else keys[li] = 0ull;
  }
  __syncthreads();
  for (int ks = 2; ks <= MPAD; ks <<= 1) {
    for (int jj = ks >> 1; jj > 0; jj >>= 1) {
      for (int idx = tid; idx < MPAD; idx += 256) {
        int l = idx ^ jj;
        if (l > idx) {
          unsigned long long a = keys[idx], bq = keys[l];
          if (((idx & ks) == 0) ? (a < bq) : (a > bq)) {
            keys[idx] = bq;
            keys[l] = a;
          }
        }
      }
      __syncthreads();
    }
  }
  int kk = (nvv + 1) >> 1;
  for (int p = tid; p < kk; p += 256) {
    int j = (int)(~(unsigned)(keys[p] & 0xFFFFFFFFull));
    float sj = v[j];
    out[i * N + j] = 1.f / (1.f + expf(-sj));
    if (wk) out[N * N + i * N + j] = 1.f;
  }
}

// ============ kG: restore invariant for g_B ==============
__global__ void kG() {
  int idx = blockIdx.x * blockDim.x + threadIdx.x;
  if (idx < N * NW) g_B[idx] = 0u;
}

// ---------------- launch ----------------
extern "C" void kernel_launch(void* const* d_in, const int* in_sizes, int n_in,
                              void* d_out, int out_size) {
  const float* x   = (const float*)d_in[0];
  const float* xo  = (const float*)d_in[1];
  const int*   ei  = (const int*)d_in[2];
  const float* W1  = (const float*)d_in[4];
  const float* a1  = (const float*)d_in[5];
  const float* a2  = (const float*)d_in[6];
  const float* b1  = (const float*)d_in[7];
  const float* w2  = (const float*)d_in[8];
  const float* as2 = (const float*)d_in[9];
  const float* ad2 = (const float*)d_in[10];
  const float* b2  = (const float*)d_in[11];
  float* out = (float*)d_out;
  int wk = (out_size >= 2 * N * N) ? 1 : 0;

  kA<<<HD + N + (E2 + 255) / 256, 256>>>(W1, a1, a2, b1, w2, xo, ei);
  kB<<<481 + 192, 256>>>(W1, w2, xo, x);
  kC<<<(E2 + 255) / 256, 256>>>(ei);
  kD<<<N, 128>>>(x);
  kE<<<576, 256>>>();
  kF<<<N, 256>>>(as2, ad2, b2, out, wk);
  kG<<<(N * NW + 255) / 256, 256>>>();
}

// round 6
// speedup vs baseline: 1.2878x; 1.0152x over previous
#include <cuda_runtime.h>
#include <math.h>

#define N 1536
#define EE 24576
#define E2 (EE + N)
#define HD 128
#define DD 1280
#define NW 48   // N/32 bitmask words per row
#define ZU 20   // split-K depth for U

// ---------------- device scratch (no allocations allowed) ----------------
// Invariant: g_cntT/g_cntS are ZERO at entry (zeroed in kC tail; load-time zero).
__device__ float g_wa[HD], g_wb[HD], g_c2[N];
__device__ float g_sa[N], g_da[N];
__device__ float g_U[HD * N];            // (128,1536)
__device__ float g_Up[ZU * HD * N];      // split-K partials (15.7 MB)
__device__ float g_xg[N * HD];           // P @ x
__device__ float g_H2[N * N];            // xg @ U partial (K 0..63)
__device__ float g_H2b[N * N];           // xg @ U partial (K 64..127)
__device__ int   g_cntT[N], g_offT[N + 1], g_curT[N];
__device__ int   g_cntS[N], g_offS[N + 1], g_curS[N];
__device__ int   g_srcT[E2];             // CSR by target (incl self loops)
__device__ int   g_tgtS[EE];             // CSR by source (original edges)
__device__ unsigned g_B[N * NW];         // B[t] = in-neighbor mask (plain stores)

__device__ __forceinline__ float lrelu(float v) { return v > 0.f ? v : 0.2f * v; }
__device__ __forceinline__ unsigned fenc(float f) {
  unsigned u = __float_as_uint(f);
  return (u & 0x80000000u) ? ~u : (u | 0x80000000u);
}
__device__ __forceinline__ float fdec(unsigned u) {
  return (u & 0x80000000u) ? __uint_as_float(u & 0x7FFFFFFFu) : __uint_as_float(~u);
}
#define ENC_NEG_INF 0x007FFFFFu

__device__ __forceinline__ float blockSum256(float v, float* sh) {
  __syncthreads();
  #pragma unroll
  for (int o = 16; o; o >>= 1) v += __shfl_xor_sync(0xFFFFFFFFu, v, o);
  if ((threadIdx.x & 31) == 0) sh[threadIdx.x >> 5] = v;
  __syncthreads();
  if (threadIdx.x < 32) {
    v = (threadIdx.x < 8) ? sh[threadIdx.x] : 0.f;
    #pragma unroll
    for (int o = 4; o; o >>= 1) v += __shfl_xor_sync(0xFFFFFFFFu, v, o);
  }
  return v;
}

// ============ kA: vec1 (0..HD+N-1) + edge degree counts ====================
__global__ __launch_bounds__(256) void kA(const float* __restrict__ W1,
                                          const float* __restrict__ a1,
                                          const float* __restrict__ a2,
                                          const float* __restrict__ b1,
                                          const float* __restrict__ w2,
                                          const float* __restrict__ xo,
                                          const int* __restrict__ ei) {
  __shared__ float sh[8];
  int b = blockIdx.x, tid = threadIdx.x;
  if (b < HD) {
    float s1 = 0.f, s2 = 0.f;
    for (int d = tid; d < DD; d += 256) {
      float w = W1[b * DD + d];
      s1 += w * a1[d]; s2 += w * a2[d];
    }
    float r1 = blockSum256(s1, sh);
    float r2 = blockSum256(s2, sh);
    if (tid == 0) { g_wa[b] = r1; g_wb[b] = r2; }
  } else if (b < HD + N) {
    int j = b - HD;
    float s = 0.f;
    for (int d = tid; d < DD; d += 256) s += b1[d] * w2[d] * xo[j * DD + d];
    float r = blockSum256(s, sh);
    if (tid == 0) g_c2[j] = r;
  } else {
    int idx = (b - (HD + N)) * 256 + tid;
    if (idx < E2) {
      if (idx < EE) {
        atomicAdd(&g_cntS[ei[idx]], 1);
        atomicAdd(&g_cntT[ei[EE + idx]], 1);
      } else {
        atomicAdd(&g_cntT[idx - EE], 1);
      }
    }
  }
}

// ============ kB: U-partials (0..479) + scan (480) + sada (481..672) =======
__global__ __launch_bounds__(256, 2) void kB(const float* __restrict__ W1,
                                             const float* __restrict__ w2,
                                             const float* __restrict__ xo,
                                             const float* __restrict__ x) {
  int b = blockIdx.x, tid = threadIdx.x;
  if (b < 24 * ZU) {
    // U partial: 64(m) x 128(j) tile, K-chunk 64, plain-store partials
    __shared__ float As[2][16][65];
    __shared__ float Bs[2][16][129];
    int tileid = b % 24;
    int z = b / 24;
    int j0 = (tileid % 12) * 128;
    int m0 = (tileid / 12) * 64;
    int k0 = z * 64;
    int tx = tid & 15, ty = tid >> 4;
    float acc[4][8];
    #pragma unroll
    for (int u = 0; u < 4; u++)
      #pragma unroll
      for (int w = 0; w < 8; w++) acc[u][w] = 0.f;
    auto load = [&](int buf, int kc) {
      #pragma unroll
      for (int l = tid; l < 64 * 16; l += 256) {
        int k = l & 15, m = l >> 4;
        As[buf][k][m] = W1[(m0 + m) * DD + k0 + kc + k] * w2[k0 + kc + k];
      }
      #pragma unroll
      for (int l = tid; l < 128 * 16; l += 256) {
        int k = l & 15, j = l >> 4;
        Bs[buf][k][j] = xo[(j0 + j) * DD + k0 + kc + k];
      }
    };
    load(0, 0);
    __syncthreads();
    for (int c = 0; c < 4; c++) {
      int buf = c & 1;
      if (c < 3) load(buf ^ 1, (c + 1) * 16);
      #pragma unroll
      for (int kk = 0; kk < 16; kk++) {
        float ra[4], rb[8];
        #pragma unroll
        for (int u = 0; u < 4; u++) ra[u] = As[buf][kk][u * 16 + ty];
        #pragma unroll
        for (int w = 0; w < 8; w++) rb[w] = Bs[buf][kk][w * 16 + tx];
        #pragma unroll
        for (int u = 0; u < 4; u++)
          #pragma unroll
          for (int w = 0; w < 8; w++) acc[u][w] += ra[u] * rb[w];
      }
      __syncthreads();
    }
    float* Up = g_Up + z * (HD * N);
    #pragma unroll
    for (int u = 0; u < 4; u++)
      #pragma unroll
      for (int w = 0; w < 8; w++)
        Up[(m0 + u * 16 + ty) * N + j0 + w * 16 + tx] = acc[u][w];
  } else if (b == 24 * ZU) {
    // exclusive scans of cntT / cntS
    __shared__ int part[256];
    int base = tid * 6;
    {
      int a[6]; int s = 0;
      #pragma unroll
      for (int u = 0; u < 6; u++) { a[u] = g_cntT[base + u]; s += a[u]; }
      part[tid] = s;
      __syncthreads();
      for (int o = 1; o < 256; o <<= 1) {
        int v = (tid >= o) ? part[tid - o] : 0;
        __syncthreads();
        part[tid] += v;
        __syncthreads();
      }
      int excl = part[tid] - s;
      #pragma unroll
      for (int u = 0; u < 6; u++) {
        g_offT[base + u] = excl; g_curT[base + u] = excl; excl += a[u];
      }
      if (tid == 255) g_offT[N] = part[255];
      __syncthreads();
    }
    {
      int a[6]; int s = 0;
      #pragma unroll
      for (int u = 0; u < 6; u++) { a[u] = g_cntS[base + u]; s += a[u]; }
      part[tid] = s;
      __syncthreads();
      for (int o = 1; o < 256; o <<= 1) {
        int v = (tid >= o) ? part[tid - o] : 0;
        __syncthreads();
        part[tid] += v;
        __syncthreads();
      }
      int excl = part[tid] - s;
      #pragma unroll
      for (int u = 0; u < 6; u++) {
        g_offS[base + u] = excl; g_curS[base + u] = excl; excl += a[u];
      }
      if (tid == 255) g_offS[N] = part[255];
    }
  } else {
    // sada: warp per node
    int node = (b - (24 * ZU + 1)) * 8 + (tid >> 5);
    int lane = tid & 31;
    if (node < N) {
      float s1 = 0.f, s2 = 0.f;
      #pragma unroll
      for (int k = lane; k < HD; k += 32) {
        float xv = x[node * HD + k];
        s1 += xv * g_wa[k]; s2 += xv * g_wb[k];
      }
      #pragma unroll
      for (int o = 16; o; o >>= 1) {
        s1 += __shfl_xor_sync(0xFFFFFFFFu, s1, o);
        s2 += __shfl_xor_sync(0xFFFFFFFFu, s2, o);
      }
      if (lane == 0) { g_sa[node] = s1; g_da[node] = s2; }
    }
  }
}

// ============ kC: U reduce (0..767) + CSR fill + cnt re-zero ===============
__global__ __launch_bounds__(256) void kC(const int* __restrict__ ei) {
  int b = blockIdx.x, tid = threadIdx.x;
  if (b < 768) {
    int idx = b * 256 + tid;   // < HD*N = 196608
    float s = 0.f;
    #pragma unroll
    for (int z = 0; z < ZU; z++) s += g_Up[z * (HD * N) + idx];
    g_U[idx] = s;
    if (idx < N) { g_cntT[idx] = 0; g_cntS[idx] = 0; }  // restore invariant
  } else {
    int idx = (b - 768) * 256 + tid;
    if (idx >= E2) return;
    int s, t;
    if (idx < EE) { s = ei[idx]; t = ei[EE + idx]; }
    else { s = t = idx - EE; }
    int pos = atomicAdd(&g_curT[t], 1);
    g_srcT[pos] = s;
    if (idx < EE) {
      int ps = atomicAdd(&g_curS[s], 1);
      g_tgtS[ps] = t;
    }
  }
}

// ======= kD: fused GAT-1 softmax + xg = P@x (0..1535) + B build (1536..) ===
__global__ __launch_bounds__(128) void kD(const float* __restrict__ x) {
  int b = blockIdx.x, tid = threadIdx.x;
  if (b < N) {
    int t = b;
    __shared__ int   ss[256];
    __shared__ float sw[256];
    __shared__ float sh[4];
    int p0 = g_offT[t], p1 = g_offT[t + 1];
    float dt = g_da[t];
    float m = -3.4e38f;
    for (int p = p0 + tid; p < p1; p += 128)
      m = fmaxf(m, lrelu(g_sa[g_srcT[p]] + dt));
    #pragma unroll
    for (int o = 16; o; o >>= 1) m = fmaxf(m, __shfl_xor_sync(0xFFFFFFFFu, m, o));
    if ((tid & 31) == 0) sh[tid >> 5] = m;
    __syncthreads();
    m = fmaxf(fmaxf(sh[0], sh[1]), fmaxf(sh[2], sh[3]));
    float acc = 0.f, dsum = 0.f;
    for (int base = p0; base < p1; base += 256) {
      int nc = min(256, p1 - base);
      for (int q = tid; q < nc; q += 128) {
        int s = g_srcT[base + q];
        float w = expf(lrelu(g_sa[s] + dt) - m);
        ss[q] = s;
        sw[q] = w;
        dsum += w;
      }
      __syncthreads();
      for (int q = 0; q < nc; q++)
        acc += sw[q] * x[ss[q] * HD + tid];
      __syncthreads();
    }
    float den = dsum;
    #pragma unroll
    for (int o = 16; o; o >>= 1) den += __shfl_xor_sync(0xFFFFFFFFu, den, o);
    if ((tid & 31) == 0) sh[tid >> 5] = den;
    __syncthreads();
    den = sh[0] + sh[1] + sh[2] + sh[3];
    g_xg[t * HD + tid] = acc / den;
  } else {
    // build B[t] from CSR-T with plain stores (self-loop inclusion harmless)
    __shared__ unsigned bw[128 * 49];
    int t = (b - N) * 128 + tid;
    unsigned* row = &bw[tid * 49];
    #pragma unroll
    for (int w = 0; w < NW; w++) row[w] = 0u;
    int p0 = g_offT[t], p1 = g_offT[t + 1];
    for (int p = p0; p < p1; p++) {
      int s = g_srcT[p];
      row[s >> 5] |= 1u << (s & 31);
    }
    #pragma unroll
    for (int w = 0; w < NW; w++) g_B[t * NW + w] = row[w];
  }
}

// ============ kE: H2 partials = xg @ U (64x128 tiles, split-K=2) ===========
__global__ __launch_bounds__(256, 2) void kE() {
  __shared__ float As[2][16][65];
  __shared__ float Bs[2][16][129];
  int b = blockIdx.x;
  int tile = b % 288;
  int z = b / 288;
  int j0 = (tile % 12) * 128;
  int m0 = (tile / 12) * 64;
  int k0 = z * 64;
  int tid = threadIdx.x, tx = tid & 15, ty = tid >> 4;
  float acc[4][8];
  #pragma unroll
  for (int u = 0; u < 4; u++)
    #pragma unroll
    for (int w = 0; w < 8; w++) acc[u][w] = 0.f;
  auto load = [&](int buf, int kc) {
    #pragma unroll
    for (int l = tid; l < 64 * 16; l += 256) {
      int k = l & 15, m = l >> 4;
      As[buf][k][m] = g_xg[(m0 + m) * HD + k0 + kc + k];
    }
    #pragma unroll
    for (int l = tid; l < 16 * 128; l += 256) {
      int j = l & 127, k = l >> 7;
      Bs[buf][k][j] = g_U[(k0 + kc + k) * N + j0 + j];
    }
  };
  load(0, 0);
  __syncthreads();
  for (int c = 0; c < 4; c++) {
    int buf = c & 1;
    if (c < 3) load(buf ^ 1, (c + 1) * 16);
    #pragma unroll
    for (int kk = 0; kk < 16; kk++) {
      float ra[4], rb[8];
      #pragma unroll
      for (int u = 0; u < 4; u++) ra[u] = As[buf][kk][u * 16 + ty];
      #pragma unroll
      for (int w = 0; w < 8; w++) rb[w] = Bs[buf][kk][w * 16 + tx];
      #pragma unroll
      for (int u = 0; u < 4; u++)
        #pragma unroll
        for (int w = 0; w < 8; w++) acc[u][w] += ra[u] * rb[w];
    }
    __syncthreads();
  }
  float* outp = z ? g_H2b : g_H2;
  #pragma unroll
  for (int u = 0; u < 4; u++)
    #pragma unroll
    for (int w = 0; w < 8; w++)
      outp[(m0 + u * 16 + ty) * N + j0 + w * 16 + tx] = acc[u][w];
}

// == kF: per-row 2-hop mask + attention + radix-select top-k + output =======
__global__ __launch_bounds__(256) void kF(const float* __restrict__ pas2,
                                          const float* __restrict__ pad2,
                                          const float* __restrict__ pb2,
                                          float* __restrict__ out, int wk) {
  int i = blockIdx.x, tid = threadIdx.x;
  __shared__ float v[N];
  __shared__ int vlist[N];
  __shared__ __align__(16) char pool[18432];
  __shared__ unsigned mb[NW];
  __shared__ int wcnt[NW + 1];
  __shared__ int hist[256];
  __shared__ unsigned s_pfx;
  __shared__ int s_rem;
  unsigned* m2 = (unsigned*)pool;
  float* den = (float*)(pool + 6144);
  float* num = (float*)(pool + 12288);
  unsigned* k32 = (unsigned*)pool;   // reuses m2 space after passes

  float as2 = pas2[0], ad2 = pad2[0], b2 = pb2[0];

  if (tid < NW) {
    unsigned w = g_B[i * NW + tid];
    if (tid == (i >> 5)) w |= 1u << (i & 31);
    mb[tid] = w;
  }
  for (int j = tid; j < N; j += 256) {
    v[j] = g_H2[i * N + j] + g_H2b[i * N + j] + g_c2[j];
    m2[j] = ENC_NEG_INF;
    den[j] = 0.f;
    num[j] = 0.f;
    out[i * N + j] = 0.f;
    if (wk) out[N * N + i * N + j] = 0.f;
  }
  __syncthreads();
  // 1-hop list
  if (tid < NW) wcnt[tid] = __popc(mb[tid]);
  __syncthreads();
  if (tid == 0) {
    int s = 0;
    for (int w = 0; w < NW; w++) { int c = wcnt[w]; wcnt[w] = s; s += c; }
    wcnt[NW] = s;
  }
  __syncthreads();
  int nk = wcnt[NW];
  if (tid < NW) {
    unsigned b = mb[tid]; int o = wcnt[tid];
    while (b) { int t = __ffs(b) - 1; b &= b - 1; vlist[o++] = tid * 32 + t; }
  }
  __syncthreads();
  // 2-hop
  if (tid < 4 * NW) {
    int sy = tid / NW, cx = tid % NW;
    unsigned acc = 0u;
    for (int q = sy; q < nk; q += 4) acc |= g_B[vlist[q] * NW + cx];
    atomicOr(&mb[cx], acc);
  }
  __syncthreads();
  // valid list (ascending index order — needed for stable tie-break)
  if (tid < NW) wcnt[tid] = __popc(mb[tid]);
  __syncthreads();
  if (tid == 0) {
    int s = 0;
    for (int w = 0; w < NW; w++) { int c = wcnt[w]; wcnt[w] = s; s += c; }
    wcnt[NW] = s;
  }
  __syncthreads();
  int nvv = wcnt[NW];
  if (tid < NW) {
    unsigned b = mb[tid]; int o = wcnt[tid];
    while (b) { int t = __ffs(b) - 1; b &= b - 1; vlist[o++] = tid * 32 + t; }
  }
  __syncthreads();
  // pass A: per-target max over valid edges
  for (int li = tid; li < nvv; li += 256) {
    int k = vlist[li];
    float vk = v[k];
    atomicMax(&m2[k], fenc(lrelu((as2 + ad2) * vk)));
    int p0 = g_offS[k], p1 = g_offS[k + 1];
    for (int p = p0; p < p1; p++) {
      int t = g_tgtS[p];
      if ((mb[t >> 5] >> (t & 31)) & 1u)
        atomicMax(&m2[t], fenc(lrelu(as2 * vk + ad2 * v[t])));
    }
  }
  __syncthreads();
  // pass B: exp-sum and weighted sum
  for (int li = tid; li < nvv; li += 256) {
    int k = vlist[li];
    float vk = v[k];
    {
      float w = expf(lrelu((as2 + ad2) * vk) - fdec(m2[k]));
      atomicAdd(&den[k], w);
      atomicAdd(&num[k], w * vk);
    }
    int p0 = g_offS[k], p1 = g_offS[k + 1];
    for (int p = p0; p < p1; p++) {
      int t = g_tgtS[p];
      if ((mb[t >> 5] >> (t & 31)) & 1u) {
        float w = expf(lrelu(as2 * vk + ad2 * v[t]) - fdec(m2[t]));
        atomicAdd(&den[t], w);
        atomicAdd(&num[t], w * vk);
      }
    }
  }
  __syncthreads();
  // scores into v, then pack 32-bit keys in list order (k32 aliases m2)
  for (int li = tid; li < nvv; li += 256) {
    int j = vlist[li];
    float sc = num[j] / fmaxf(den[j], 1e-12f) + b2;
    v[j] = sc;
  }
  __syncthreads();
  for (int li = tid; li < nvv; li += 256)
    k32[li] = fenc(v[vlist[li]]);
  int kk = (nvv + 1) >> 1;
  if (tid == 0) { s_rem = kk; s_pfx = 0u; }
  __syncthreads();
  // radix-select the kk-th largest key (4 rounds of 8 bits, high to low)
  for (int r = 0; r < 4; r++) {
    int shift = 24 - 8 * r;
    if (tid < 256) hist[tid] = 0;
    __syncthreads();
    unsigned pfx = s_pfx;
    for (int li = tid; li < nvv; li += 256) {
      unsigned key = k32[li];
      bool cand;
      if (r == 0) cand = true;
      else cand = ((key >> (shift + 8)) == pfx);
      if (cand) atomicAdd(&hist[(key >> shift) & 255], 1);
    }
    __syncthreads();
    if (tid < 32) {
      int s = 0;
      #pragma unroll
      for (int u = 0; u < 8; u++) s += hist[tid * 8 + u];
      int cum = s;
      #pragma unroll
      for (int o = 1; o < 32; o <<= 1) {
        int t2 = __shfl_down_sync(0xFFFFFFFFu, cum, o);
        if (tid + o < 32) cum += t2;
      }
      int run = cum - s;            // count in buckets >= 8*(tid+1)
      int rem = s_rem;
      unsigned pfxold = s_pfx;
      int fb = -1, frem = 0;
      for (int bb = tid * 8 + 7; bb >= tid * 8; bb--) {
        int h = hist[bb];
        if (run < rem && rem <= run + h) { fb = bb; frem = rem - run; }
        run += h;
      }
      __syncwarp();
      if (fb >= 0) { s_pfx = (pfxold << 8) | (unsigned)fb; s_rem = frem; }
    }
    __syncthreads();
  }
  unsigned T = s_pfx;
  int rem = s_rem;
  // keep: key > T, or key == T with tie-rank (by ascending index) < rem
  for (int li = tid; li < nvv; li += 256) {
    unsigned key = k32[li];
    bool keep = key > T;
    if (!keep && key == T) {
      int cnt = 0;
      for (int l2 = 0; l2 < li; l2++) cnt += (k32[l2] == T);
      keep = cnt < rem;
    }
    if (keep) {
      int j = vlist[li];
      float sj = v[j];
      out[i * N + j] = 1.f / (1.f + expf(-sj));
      if (wk) out[N * N + i * N + j] = 1.f;
    }
  }
}

// ---------------- launch ----------------
extern "C" void kernel_launch(void* const* d_in, const int* in_sizes, int n_in,
                              void* d_out, int out_size) {
  const float* x   = (const float*)d_in[0];
  const float* xo  = (const float*)d_in[1];
  const int*   ei  = (const int*)d_in[2];
  const float* W1  = (const float*)d_in[4];
  const float* a1  = (const float*)d_in[5];
  const float* a2  = (const float*)d_in[6];
  const float* b1  = (const float*)d_in[7];
  const float* w2  = (const float*)d_in[8];
  const float* as2 = (const float*)d_in[9];
  const float* ad2 = (const float*)d_in[10];
  const float* b2  = (const float*)d_in[11];
  float* out = (float*)d_out;
  int wk = (out_size >= 2 * N * N) ? 1 : 0;

  kA<<<HD + N + (E2 + 255) / 256, 256>>>(W1, a1, a2, b1, w2, xo, ei);
  kB<<<24 * ZU + 1 + 192, 256>>>(W1, w2, xo, x);
  kC<<<768 + (E2 + 255) / 256, 256>>>(ei);
  kD<<<N + N / 128, 128>>>(x);
  kE<<<576, 256>>>();
  kF<<<N, 256>>>(as2, ad2, b2, out, wk);
}

// round 7
// speedup vs baseline: 1.6027x; 1.2446x over previous
#include <cuda_runtime.h>
#include <math.h>

#define N 1536
#define EE 24576
#define E2 (EE + N)
#define HD 128
#define DD 1280
#define NW 48   // N/32 bitmask words per row
#define ZU 20   // split-K depth for U

// ---------------- device scratch (no allocations allowed) ----------------
// Invariant: g_cntT/g_cntS are ZERO at entry (zeroed in kC; load-time zero).
// g_B is zeroed by kA blocks each run before kC fills it.
__device__ float g_wa[HD], g_wb[HD], g_c2[N];
__device__ float g_sa[N], g_da[N];
__device__ float g_U[HD * N];            // (128,1536)
__device__ float g_Up[ZU * HD * N];      // split-K partials (15.7 MB)
__device__ float g_xg[N * HD];           // P @ x
__device__ float g_H2[N * N];            // xg @ U partial (K 0..63)
__device__ float g_H2b[N * N];           // xg @ U partial (K 64..127)
__device__ int   g_cntT[N], g_offT[N + 1], g_curT[N];
__device__ int   g_cntS[N], g_offS[N + 1], g_curS[N];
__device__ int   g_srcT[E2];             // CSR by target (incl self loops)
__device__ int   g_tgtS[EE];             // CSR by source (unused by kF now)
__device__ unsigned g_B[N * NW];         // B[t] = in-neighbor mask

__device__ __forceinline__ float lrelu(float v) { return v > 0.f ? v : 0.2f * v; }
__device__ __forceinline__ unsigned fenc(float f) {
  unsigned u = __float_as_uint(f);
  return (u & 0x80000000u) ? ~u : (u | 0x80000000u);
}

__device__ __forceinline__ float blockSum256(float v, float* sh) {
  __syncthreads();
  #pragma unroll
  for (int o = 16; o; o >>= 1) v += __shfl_xor_sync(0xFFFFFFFFu, v, o);
  if ((threadIdx.x & 31) == 0) sh[threadIdx.x >> 5] = v;
  __syncthreads();
  if (threadIdx.x < 32) {
    v = (threadIdx.x < 8) ? sh[threadIdx.x] : 0.f;
    #pragma unroll
    for (int o = 4; o; o >>= 1) v += __shfl_xor_sync(0xFFFFFFFFu, v, o);
  }
  return v;
}

// ====== kA: vec1 (0..HD+N-1) + edge degree counts + g_B zero ===============
__global__ __launch_bounds__(256) void kA(const float* __restrict__ W1,
                                          const float* __restrict__ a1,
                                          const float* __restrict__ a2,
                                          const float* __restrict__ b1,
                                          const float* __restrict__ w2,
                                          const float* __restrict__ xo,
                                          const int* __restrict__ ei) {
  __shared__ float sh[8];
  int b = blockIdx.x, tid = threadIdx.x;
  if (b < HD) {
    float s1 = 0.f, s2 = 0.f;
    for (int d = tid; d < DD; d += 256) {
      float w = W1[b * DD + d];
      s1 += w * a1[d]; s2 += w * a2[d];
    }
    float r1 = blockSum256(s1, sh);
    float r2 = blockSum256(s2, sh);
    if (tid == 0) { g_wa[b] = r1; g_wb[b] = r2; }
  } else if (b < HD + N) {
    int j = b - HD;
    float s = 0.f;
    for (int d = tid; d < DD; d += 256) s += b1[d] * w2[d] * xo[j * DD + d];
    float r = blockSum256(s, sh);
    if (tid == 0) g_c2[j] = r;
  } else if (b < HD + N + (E2 / 256)) {
    int idx = (b - (HD + N)) * 256 + tid;
    if (idx < EE) {
      atomicAdd(&g_cntS[ei[idx]], 1);
      atomicAdd(&g_cntT[ei[EE + idx]], 1);
    } else {
      atomicAdd(&g_cntT[idx - EE], 1);
    }
  } else {
    int idx = (b - (HD + N + E2 / 256)) * 256 + tid;
    g_B[idx] = 0u;   // N*NW = 73728 = 288*256
  }
}

// ============ kB: U-partials (0..479) + scan (480) + sada (481..672) =======
__global__ __launch_bounds__(256, 2) void kB(const float* __restrict__ W1,
                                             const float* __restrict__ w2,
                                             const float* __restrict__ xo,
                                             const float* __restrict__ x) {
  int b = blockIdx.x, tid = threadIdx.x;
  if (b < 24 * ZU) {
    __shared__ float As[2][16][65];
    __shared__ float Bs[2][16][129];
    int tileid = b % 24;
    int z = b / 24;
    int j0 = (tileid % 12) * 128;
    int m0 = (tileid / 12) * 64;
    int k0 = z * 64;
    int tx = tid & 15, ty = tid >> 4;
    float acc[4][8];
    #pragma unroll
    for (int u = 0; u < 4; u++)
      #pragma unroll
      for (int w = 0; w < 8; w++) acc[u][w] = 0.f;
    auto load = [&](int buf, int kc) {
      #pragma unroll
      for (int l = tid; l < 64 * 16; l += 256) {
        int k = l & 15, m = l >> 4;
        As[buf][k][m] = W1[(m0 + m) * DD + k0 + kc + k] * w2[k0 + kc + k];
      }
      #pragma unroll
      for (int l = tid; l < 128 * 16; l += 256) {
        int k = l & 15, j = l >> 4;
        Bs[buf][k][j] = xo[(j0 + j) * DD + k0 + kc + k];
      }
    };
    load(0, 0);
    __syncthreads();
    for (int c = 0; c < 4; c++) {
      int buf = c & 1;
      if (c < 3) load(buf ^ 1, (c + 1) * 16);
      #pragma unroll
      for (int kk = 0; kk < 16; kk++) {
        float ra[4], rb[8];
        #pragma unroll
        for (int u = 0; u < 4; u++) ra[u] = As[buf][kk][u * 16 + ty];
        #pragma unroll
        for (int w = 0; w < 8; w++) rb[w] = Bs[buf][kk][w * 16 + tx];
        #pragma unroll
        for (int u = 0; u < 4; u++)
          #pragma unroll
          for (int w = 0; w < 8; w++) acc[u][w] += ra[u] * rb[w];
      }
      __syncthreads();
    }
    float* Up = g_Up + z * (HD * N);
    #pragma unroll
    for (int u = 0; u < 4; u++)
      #pragma unroll
      for (int w = 0; w < 8; w++)
        Up[(m0 + u * 16 + ty) * N + j0 + w * 16 + tx] = acc[u][w];
  } else if (b == 24 * ZU) {
    __shared__ int part[256];
    int base = tid * 6;
    {
      int a[6]; int s = 0;
      #pragma unroll
      for (int u = 0; u < 6; u++) { a[u] = g_cntT[base + u]; s += a[u]; }
      part[tid] = s;
      __syncthreads();
      for (int o = 1; o < 256; o <<= 1) {
        int v = (tid >= o) ? part[tid - o] : 0;
        __syncthreads();
        part[tid] += v;
        __syncthreads();
      }
      int excl = part[tid] - s;
      #pragma unroll
      for (int u = 0; u < 6; u++) {
        g_offT[base + u] = excl; g_curT[base + u] = excl; excl += a[u];
      }
      if (tid == 255) g_offT[N] = part[255];
      __syncthreads();
    }
    {
      int a[6]; int s = 0;
      #pragma unroll
      for (int u = 0; u < 6; u++) { a[u] = g_cntS[base + u]; s += a[u]; }
      part[tid] = s;
      __syncthreads();
      for (int o = 1; o < 256; o <<= 1) {
        int v = (tid >= o) ? part[tid - o] : 0;
        __syncthreads();
        part[tid] += v;
        __syncthreads();
      }
      int excl = part[tid] - s;
      #pragma unroll
      for (int u = 0; u < 6; u++) {
        g_offS[base + u] = excl; g_curS[base + u] = excl; excl += a[u];
      }
      if (tid == 255) g_offS[N] = part[255];
    }
  } else {
    int node = (b - (24 * ZU + 1)) * 8 + (tid >> 5);
    int lane = tid & 31;
    if (node < N) {
      float s1 = 0.f, s2 = 0.f;
      #pragma unroll
      for (int k = lane; k < HD; k += 32) {
        float xv = x[node * HD + k];
        s1 += xv * g_wa[k]; s2 += xv * g_wb[k];
      }
      #pragma unroll
      for (int o = 16; o; o >>= 1) {
        s1 += __shfl_xor_sync(0xFFFFFFFFu, s1, o);
        s2 += __shfl_xor_sync(0xFFFFFFFFu, s2, o);
      }
      if (lane == 0) { g_sa[node] = s1; g_da[node] = s2; }
    }
  }
}

// ====== kC: U reduce (0..767) + CSR fill + B build + cnt re-zero ===========
__global__ __launch_bounds__(256) void kC(const int* __restrict__ ei) {
  int b = blockIdx.x, tid = threadIdx.x;
  if (b < 768) {
    int idx = b * 256 + tid;   // < HD*N = 196608
    float s = 0.f;
    #pragma unroll
    for (int z = 0; z < ZU; z++) s += g_Up[z * (HD * N) + idx];
    g_U[idx] = s;
    if (idx < N) { g_cntT[idx] = 0; g_cntS[idx] = 0; }  // restore invariant
  } else {
    int idx = (b - 768) * 256 + tid;
    if (idx >= E2) return;
    int s, t;
    if (idx < EE) { s = ei[idx]; t = ei[EE + idx]; }
    else { s = t = idx - EE; }
    int pos = atomicAdd(&g_curT[t], 1);
    g_srcT[pos] = s;
    if (idx < EE) {
      int ps = atomicAdd(&g_curS[s], 1);
      g_tgtS[ps] = t;
      atomicOr(&g_B[t * NW + (s >> 5)], 1u << (s & 31));
    }
  }
}

// ============ kD: fused GAT-1 softmax + xg = P@x (block per target) ========
__global__ __launch_bounds__(128) void kD(const float* __restrict__ x) {
  int t = blockIdx.x, tid = threadIdx.x;
  __shared__ int   ss[256];
  __shared__ float sw[256];
  __shared__ float sh[4];
  int p0 = g_offT[t], p1 = g_offT[t + 1];
  float dt = g_da[t];
  float m = -3.4e38f;
  for (int p = p0 + tid; p < p1; p += 128)
    m = fmaxf(m, lrelu(g_sa[g_srcT[p]] + dt));
  #pragma unroll
  for (int o = 16; o; o >>= 1) m = fmaxf(m, __shfl_xor_sync(0xFFFFFFFFu, m, o));
  if ((tid & 31) == 0) sh[tid >> 5] = m;
  __syncthreads();
  m = fmaxf(fmaxf(sh[0], sh[1]), fmaxf(sh[2], sh[3]));
  float acc = 0.f, dsum = 0.f;
  for (int base = p0; base < p1; base += 256) {
    int nc = min(256, p1 - base);
    for (int q = tid; q < nc; q += 128) {
      int s = g_srcT[base + q];
      float w = expf(lrelu(g_sa[s] + dt) - m);
      ss[q] = s;
      sw[q] = w;
      dsum += w;
    }
    __syncthreads();
    for (int q = 0; q < nc; q++)
      acc += sw[q] * x[ss[q] * HD + tid];
    __syncthreads();
  }
  float den = dsum;
  #pragma unroll
  for (int o = 16; o; o >>= 1) den += __shfl_xor_sync(0xFFFFFFFFu, den, o);
  if ((tid & 31) == 0) sh[tid >> 5] = den;
  __syncthreads();
  den = sh[0] + sh[1] + sh[2] + sh[3];
  g_xg[t * HD + tid] = acc / den;
}

// ============ kE: H2 partials = xg @ U (64x128 tiles, split-K=2) ===========
__global__ __launch_bounds__(256, 2) void kE() {
  __shared__ float As[2][16][65];
  __shared__ float Bs[2][16][129];
  int b = blockIdx.x;
  int tile = b % 288;
  int z = b / 288;
  int j0 = (tile % 12) * 128;
  int m0 = (tile / 12) * 64;
  int k0 = z * 64;
  int tid = threadIdx.x, tx = tid & 15, ty = tid >> 4;
  float acc[4][8];
  #pragma unroll
  for (int u = 0; u < 4; u++)
    #pragma unroll
    for (int w = 0; w < 8; w++) acc[u][w] = 0.f;
  auto load = [&](int buf, int kc) {
    #pragma unroll
    for (int l = tid; l < 64 * 16; l += 256) {
      int k = l & 15, m = l >> 4;
      As[buf][k][m] = g_xg[(m0 + m) * HD + k0 + kc + k];
    }
    #pragma unroll
    for (int l = tid; l < 16 * 128; l += 256) {
      int j = l & 127, k = l >> 7;
      Bs[buf][k][j] = g_U[(k0 + kc + k) * N + j0 + j];
    }
  };
  load(0, 0);
  __syncthreads();
  for (int c = 0; c < 4; c++) {
    int buf = c & 1;
    if (c < 3) load(buf ^ 1, (c + 1) * 16);
    #pragma unroll
    for (int kk = 0; kk < 16; kk++) {
      float ra[4], rb[8];
      #pragma unroll
      for (int u = 0; u < 4; u++) ra[u] = As[buf][kk][u * 16 + ty];
      #pragma unroll
      for (int w = 0; w < 8; w++) rb[w] = Bs[buf][kk][w * 16 + tx];
      #pragma unroll
      for (int u = 0; u < 4; u++)
        #pragma unroll
        for (int w = 0; w < 8; w++) acc[u][w] += ra[u] * rb[w];
    }
    __syncthreads();
  }
  float* outp = z ? g_H2b : g_H2;
  #pragma unroll
  for (int u = 0; u < 4; u++)
    #pragma unroll
    for (int w = 0; w < 8; w++)
      outp[(m0 + u * 16 + ty) * N + j0 + w * 16 + tx] = acc[u][w];
}

// == kF: per-row 2-hop mask + GATHER attention + radix-select + output ======
__global__ __launch_bounds__(256) void kF(const float* __restrict__ pas2,
                                          const float* __restrict__ pad2,
                                          const float* __restrict__ pb2,
                                          float* __restrict__ out, int wk) {
  int i = blockIdx.x, tid = threadIdx.x;
  __shared__ float v[N];
  __shared__ int vlist[N];
  __shared__ float scl[N];       // list-indexed scores
  __shared__ unsigned k32[N];    // list-indexed keys
  __shared__ unsigned mb[NW];
  __shared__ int wcnt[NW + 1];
  __shared__ int hist[256];
  __shared__ unsigned s_pfx;
  __shared__ int s_rem;

  float as2 = pas2[0], ad2 = pad2[0], b2 = pb2[0];

  if (tid < NW) {
    unsigned w = g_B[i * NW + tid];
    if (tid == (i >> 5)) w |= 1u << (i & 31);
    mb[tid] = w;
  }
  for (int j = tid; j < N; j += 256) {
    v[j] = g_H2[i * N + j] + g_H2b[i * N + j] + g_c2[j];
    out[i * N + j] = 0.f;
    if (wk) out[N * N + i * N + j] = 0.f;
  }
  __syncthreads();
  // 1-hop list
  if (tid < NW) wcnt[tid] = __popc(mb[tid]);
  __syncthreads();
  if (tid == 0) {
    int s = 0;
    for (int w = 0; w < NW; w++) { int c = wcnt[w]; wcnt[w] = s; s += c; }
    wcnt[NW] = s;
  }
  __syncthreads();
  int nk = wcnt[NW];
  if (tid < NW) {
    unsigned b = mb[tid]; int o = wcnt[tid];
    while (b) { int t = __ffs(b) - 1; b &= b - 1; vlist[o++] = tid * 32 + t; }
  }
  __syncthreads();
  // 2-hop
  if (tid < 4 * NW) {
    int sy = tid / NW, cx = tid % NW;
    unsigned acc = 0u;
    for (int q = sy; q < nk; q += 4) acc |= g_B[vlist[q] * NW + cx];
    atomicOr(&mb[cx], acc);
  }
  __syncthreads();
  // valid list (ascending index order — stable tie-break depends on it)
  if (tid < NW) wcnt[tid] = __popc(mb[tid]);
  __syncthreads();
  if (tid == 0) {
    int s = 0;
    for (int w = 0; w < NW; w++) { int c = wcnt[w]; wcnt[w] = s; s += c; }
    wcnt[NW] = s;
  }
  __syncthreads();
  int nvv = wcnt[NW];
  if (tid < NW) {
    unsigned b = mb[tid]; int o = wcnt[tid];
    while (b) { int t = __ffs(b) - 1; b &= b - 1; vlist[o++] = tid * 32 + t; }
  }
  __syncthreads();
  // gather softmax: one thread per valid target, registers only
  for (int li = tid; li < nvv; li += 256) {
    int t = vlist[li];
    int p0 = g_offT[t], p1 = g_offT[t + 1];
    float adt = ad2 * v[t];
    float m = -3.4e38f;
    for (int p = p0; p < p1; p++) {
      int s = g_srcT[p];
      if ((mb[s >> 5] >> (s & 31)) & 1u)
        m = fmaxf(m, lrelu(as2 * v[s] + adt));
    }
    float den = 0.f, num = 0.f;
    for (int p = p0; p < p1; p++) {
      int s = g_srcT[p];
      if ((mb[s >> 5] >> (s & 31)) & 1u) {
        float vs = v[s];
        float w = expf(lrelu(as2 * vs + adt) - m);
        den += w;
        num += w * vs;
      }
    }
    float sc = num / fmaxf(den, 1e-12f) + b2;
    scl[li] = sc;
    k32[li] = fenc(sc);
  }
  int kk = (nvv + 1) >> 1;
  if (tid == 0) { s_rem = kk; s_pfx = 0u; }
  __syncthreads();
  // radix-select the kk-th largest key (4 rounds of 8 bits, high to low)
  for (int r = 0; r < 4; r++) {
    int shift = 24 - 8 * r;
    if (tid < 256) hist[tid] = 0;
    __syncthreads();
    unsigned pfx = s_pfx;
    for (int li = tid; li < nvv; li += 256) {
      unsigned key = k32[li];
      bool cand = (r == 0) || ((key >> (shift + 8)) == pfx);
      if (cand) atomicAdd(&hist[(key >> shift) & 255], 1);
    }
    __syncthreads();
    if (tid < 32) {
      int s = 0;
      #pragma unroll
      for (int u = 0; u < 8; u++) s += hist[tid * 8 + u];
      int cum = s;
      #pragma unroll
      for (int o = 1; o < 32; o <<= 1) {
        int t2 = __shfl_down_sync(0xFFFFFFFFu, cum, o);
        if (tid + o < 32) cum += t2;
      }
      int run = cum - s;            // count in buckets >= 8*(tid+1)
      int rem = s_rem;
      unsigned pfxold = s_pfx;
      int fb = -1, frem = 0;
      for (int bb = tid * 8 + 7; bb >= tid * 8; bb--) {
        int h = hist[bb];
        if (run < rem && rem <= run + h) { fb = bb; frem = rem - run; }
        run += h;
      }
      __syncwarp();
      if (fb >= 0) { s_pfx = (pfxold << 8) | (unsigned)fb; s_rem = frem; }
    }
    __syncthreads();
  }
  unsigned T = s_pfx;
  int rem = s_rem;
  // keep: key > T, or key == T with tie-rank (ascending index) < rem
  for (int li = tid; li < nvv; li += 256) {
    unsigned key = k32[li];
    bool keep = key > T;
    if (!keep && key == T) {
      int cnt = 0;
      for (int l2 = 0; l2 < li; l2++) cnt += (k32[l2] == T);
      keep = cnt < rem;
    }
    if (keep) {
      int j = vlist[li];
      float sj = scl[li];
      out[i * N + j] = 1.f / (1.f + expf(-sj));
      if (wk) out[N * N + i * N + j] = 1.f;
    }
  }
}

// ---------------- launch ----------------
extern "C" void kernel_launch(void* const* d_in, const int* in_sizes, int n_in,
                              void* d_out, int out_size) {
  const float* x   = (const float*)d_in[0];
  const float* xo  = (const float*)d_in[1];
  const int*   ei  = (const int*)d_in[2];
  const float* W1  = (const float*)d_in[4];
  const float* a1  = (const float*)d_in[5];
  const float* a2  = (const float*)d_in[6];
  const float* b1  = (const float*)d_in[7];
  const float* w2  = (const float*)d_in[8];
  const float* as2 = (const float*)d_in[9];
  const float* ad2 = (const float*)d_in[10];
  const float* b2  = (const float*)d_in[11];
  float* out = (float*)d_out;
  int wk = (out_size >= 2 * N * N) ? 1 : 0;

  kA<<<HD + N + E2 / 256 + (N * NW) / 256, 256>>>(W1, a1, a2, b1, w2, xo, ei);
  kB<<<24 * ZU + 1 + 192, 256>>>(W1, w2, xo, x);
  kC<<<768 + (E2 + 255) / 256, 256>>>(ei);
  kD<<<N, 128>>>(x);
  kE<<<576, 256>>>();
  kF<<<N, 256>>>(as2, ad2, b2, out, wk);
}

// round 8
// speedup vs baseline: 1.6241x; 1.0134x over previous
#include <cuda_runtime.h>
#include <math.h>

#define N 1536
#define EE 24576
#define E2 (EE + N)
#define HD 128
#define DD 1280
#define NW 48   // N/32 bitmask words per row
#define ZU 20   // split-K depth for U

// ---------------- device scratch (no allocations allowed) ----------------
// Invariant: g_cntT/g_cntS are ZERO at entry (re-zeroed by kFill each run;
// zero at module load). g_B is zeroed by kZero on a parallel branch before
// kFill (event-ordered).
__device__ float g_wa[HD], g_wb[HD], g_c2[N];
__device__ float g_sa[N], g_da[N];
__device__ float g_U[HD * N];            // (128,1536)
__device__ float g_Up[ZU * HD * N];      // split-K partials (15.7 MB)
__device__ float g_xg[N * HD];           // P @ x
__device__ float g_H2[N * N];            // xg @ U partial (K 0..63)
__device__ float g_H2b[N * N];           // xg @ U partial (K 64..127)
__device__ int   g_cntT[N], g_offT[N + 1], g_curT[N];
__device__ int   g_cntS[N], g_offS[N + 1], g_curS[N];
__device__ int   g_srcT[E2];             // CSR by target (incl self loops)
__device__ int   g_tgtS[EE];             // CSR by source
__device__ unsigned g_B[N * NW];         // B[t] = in-neighbor mask

__device__ __forceinline__ float lrelu(float v) { return v > 0.f ? v : 0.2f * v; }
__device__ __forceinline__ unsigned fenc(float f) {
  unsigned u = __float_as_uint(f);
  return (u & 0x80000000u) ? ~u : (u | 0x80000000u);
}

__device__ __forceinline__ float blockSum256(float v, float* sh) {
  __syncthreads();
  #pragma unroll
  for (int o = 16; o; o >>= 1) v += __shfl_xor_sync(0xFFFFFFFFu, v, o);
  if ((threadIdx.x & 31) == 0) sh[threadIdx.x >> 5] = v;
  __syncthreads();
  if (threadIdx.x < 32) {
    v = (threadIdx.x < 8) ? sh[threadIdx.x] : 0.f;
    #pragma unroll
    for (int o = 4; o; o >>= 1) v += __shfl_xor_sync(0xFFFFFFFFu, v, o);
  }
  return v;
}

// ---------- host-side fork/join resources (created before harness checkpoints)
struct HxStreams {
  cudaStream_t s1, s2, s3;
  cudaEvent_t e0, e1, e2, e3;
  HxStreams() {
    cudaStreamCreateWithFlags(&s1, cudaStreamNonBlocking);
    cudaStreamCreateWithFlags(&s2, cudaStreamNonBlocking);
    cudaStreamCreateWithFlags(&s3, cudaStreamNonBlocking);
    cudaEventCreateWithFlags(&e0, cudaEventDisableTiming);
    cudaEventCreateWithFlags(&e1, cudaEventDisableTiming);
    cudaEventCreateWithFlags(&e2, cudaEventDisableTiming);
    cudaEventCreateWithFlags(&e3, cudaEventDisableTiming);
  }
};
static HxStreams g_hs;

// ============ kZero: zero out buffer + g_B (parallel branch) ===============
__global__ void kZero(float* __restrict__ out, int out_size) {
  int i = blockIdx.x * blockDim.x + threadIdx.x;
  int stride = gridDim.x * blockDim.x;
  for (int p = i; p < out_size; p += stride) out[p] = 0.f;
  for (int p = i; p < N * NW; p += stride) g_B[p] = 0u;
}

// ============ kCount: edge degree counts ===================================
__global__ void kCount(const int* __restrict__ ei) {
  int idx = blockIdx.x * blockDim.x + threadIdx.x;
  if (idx < EE) {
    atomicAdd(&g_cntS[ei[idx]], 1);
    atomicAdd(&g_cntT[ei[EE + idx]], 1);
  } else if (idx < E2) {
    atomicAdd(&g_cntT[idx - EE], 1);
  }
}

// ============ kScan: exclusive scans of cntT / cntS ========================
__global__ void kScan() {
  __shared__ int part[256];
  int tid = threadIdx.x;
  int base = tid * 6;
  {
    int a[6]; int s = 0;
    #pragma unroll
    for (int u = 0; u < 6; u++) { a[u] = g_cntT[base + u]; s += a[u]; }
    part[tid] = s;
    __syncthreads();
    for (int o = 1; o < 256; o <<= 1) {
      int v = (tid >= o) ? part[tid - o] : 0;
      __syncthreads();
      part[tid] += v;
      __syncthreads();
    }
    int excl = part[tid] - s;
    #pragma unroll
    for (int u = 0; u < 6; u++) {
      g_offT[base + u] = excl; g_curT[base + u] = excl; excl += a[u];
    }
    if (tid == 255) g_offT[N] = part[255];
    __syncthreads();
  }
  {
    int a[6]; int s = 0;
    #pragma unroll
    for (int u = 0; u < 6; u++) { a[u] = g_cntS[base + u]; s += a[u]; }
    part[tid] = s;
    __syncthreads();
    for (int o = 1; o < 256; o <<= 1) {
      int v = (tid >= o) ? part[tid - o] : 0;
      __syncthreads();
      part[tid] += v;
      __syncthreads();
    }
    int excl = part[tid] - s;
    #pragma unroll
    for (int u = 0; u < 6; u++) {
      g_offS[base + u] = excl; g_curS[base + u] = excl; excl += a[u];
    }
    if (tid == 255) g_offS[N] = part[255];
  }
}

// ============ kFill: CSR fill + B build + cnt re-zero ======================
__global__ void kFill(const int* __restrict__ ei) {
  int idx = blockIdx.x * blockDim.x + threadIdx.x;
  if (idx < N) { g_cntT[idx] = 0; g_cntS[idx] = 0; }  // restore invariant
  if (idx >= E2) return;
  int s, t;
  if (idx < EE) { s = ei[idx]; t = ei[EE + idx]; }
  else { s = t = idx - EE; }
  int pos = atomicAdd(&g_curT[t], 1);
  g_srcT[pos] = s;
  if (idx < EE) {
    int ps = atomicAdd(&g_curS[s], 1);
    g_tgtS[ps] = t;
    atomicOr(&g_B[t * NW + (s >> 5)], 1u << (s & 31));
  }
}

// ============ kVec1: wa/wb/c2 (parallel branch) ============================
__global__ __launch_bounds__(256) void kVec1(const float* __restrict__ W1,
                                             const float* __restrict__ a1,
                                             const float* __restrict__ a2,
                                             const float* __restrict__ b1,
                                             const float* __restrict__ w2,
                                             const float* __restrict__ xo) {
  __shared__ float sh[8];
  int b = blockIdx.x, tid = threadIdx.x;
  if (b < HD) {
    float s1 = 0.f, s2 = 0.f;
    for (int d = tid; d < DD; d += 256) {
      float w = W1[b * DD + d];
      s1 += w * a1[d]; s2 += w * a2[d];
    }
    float r1 = blockSum256(s1, sh);
    float r2 = blockSum256(s2, sh);
    if (tid == 0) { g_wa[b] = r1; g_wb[b] = r2; }
  } else {
    int j = b - HD;
    float s = 0.f;
    for (int d = tid; d < DD; d += 256) s += b1[d] * w2[d] * xo[j * DD + d];
    float r = blockSum256(s, sh);
    if (tid == 0) g_c2[j] = r;
  }
}

// ============ kSada: sa/da, warp per node ==================================
__global__ __launch_bounds__(256) void kSada(const float* __restrict__ x) {
  int node = blockIdx.x * 8 + (threadIdx.x >> 5);
  int lane = threadIdx.x & 31;
  if (node >= N) return;
  float s1 = 0.f, s2 = 0.f;
  #pragma unroll
  for (int k = lane; k < HD; k += 32) {
    float xv = x[node * HD + k];
    s1 += xv * g_wa[k]; s2 += xv * g_wb[k];
  }
  #pragma unroll
  for (int o = 16; o; o >>= 1) {
    s1 += __shfl_xor_sync(0xFFFFFFFFu, s1, o);
    s2 += __shfl_xor_sync(0xFFFFFFFFu, s2, o);
  }
  if (lane == 0) { g_sa[node] = s1; g_da[node] = s2; }
}

// ============ kUp: U split-K partials (parallel branch) ====================
__global__ __launch_bounds__(256, 2) void kUp(const float* __restrict__ W1,
                                              const float* __restrict__ w2,
                                              const float* __restrict__ xo) {
  __shared__ float As[2][16][65];
  __shared__ float Bs[2][16][129];
  int b = blockIdx.x;
  int tileid = b % 24;
  int z = b / 24;
  int j0 = (tileid % 12) * 128;
  int m0 = (tileid / 12) * 64;
  int k0 = z * 64;
  int tid = threadIdx.x, tx = tid & 15, ty = tid >> 4;
  float acc[4][8];
  #pragma unroll
  for (int u = 0; u < 4; u++)
    #pragma unroll
    for (int w = 0; w < 8; w++) acc[u][w] = 0.f;
  auto load = [&](int buf, int kc) {
    #pragma unroll
    for (int l = tid; l < 64 * 16; l += 256) {
      int k = l & 15, m = l >> 4;
      As[buf][k][m] = W1[(m0 + m) * DD + k0 + kc + k] * w2[k0 + kc + k];
    }
    #pragma unroll
    for (int l = tid; l < 128 * 16; l += 256) {
      int k = l & 15, j = l >> 4;
      Bs[buf][k][j] = xo[(j0 + j) * DD + k0 + kc + k];
    }
  };
  load(0, 0);
  __syncthreads();
  for (int c = 0; c < 4; c++) {
    int buf = c & 1;
    if (c < 3) load(buf ^ 1, (c + 1) * 16);
    #pragma unroll
    for (int kk = 0; kk < 16; kk++) {
      float ra[4], rb[8];
      #pragma unroll
      for (int u = 0; u < 4; u++) ra[u] = As[buf][kk][u * 16 + ty];
      #pragma unroll
      for (int w = 0; w < 8; w++) rb[w] = Bs[buf][kk][w * 16 + tx];
      #pragma unroll
      for (int u = 0; u < 4; u++)
        #pragma unroll
        for (int w = 0; w < 8; w++) acc[u][w] += ra[u] * rb[w];
    }
    __syncthreads();
  }
  float* Up = g_Up + z * (HD * N);
  #pragma unroll
  for (int u = 0; u < 4; u++)
    #pragma unroll
    for (int w = 0; w < 8; w++)
      Up[(m0 + u * 16 + ty) * N + j0 + w * 16 + tx] = acc[u][w];
}

// ============ kUred: reduce split-K partials ===============================
__global__ void kUred() {
  int idx = blockIdx.x * blockDim.x + threadIdx.x;   // < HD*N
  float s = 0.f;
  #pragma unroll
  for (int z = 0; z < ZU; z++) s += g_Up[z * (HD * N) + idx];
  g_U[idx] = s;
}

// ============ kXg: fused GAT-1 softmax + xg = P@x (block per target) =======
__global__ __launch_bounds__(128) void kXg(const float* __restrict__ x) {
  int t = blockIdx.x, tid = threadIdx.x;
  __shared__ int   ss[256];
  __shared__ float sw[256];
  __shared__ float sh[4];
  int p0 = g_offT[t], p1 = g_offT[t + 1];
  float dt = g_da[t];
  float m = -3.4e38f;
  for (int p = p0 + tid; p < p1; p += 128)
    m = fmaxf(m, lrelu(g_sa[g_srcT[p]] + dt));
  #pragma unroll
  for (int o = 16; o; o >>= 1) m = fmaxf(m, __shfl_xor_sync(0xFFFFFFFFu, m, o));
  if ((tid & 31) == 0) sh[tid >> 5] = m;
  __syncthreads();
  m = fmaxf(fmaxf(sh[0], sh[1]), fmaxf(sh[2], sh[3]));
  float acc = 0.f, dsum = 0.f;
  for (int base = p0; base < p1; base += 256) {
    int nc = min(256, p1 - base);
    for (int q = tid; q < nc; q += 128) {
      int s = g_srcT[base + q];
      float w = expf(lrelu(g_sa[s] + dt) - m);
      ss[q] = s;
      sw[q] = w;
      dsum += w;
    }
    __syncthreads();
    for (int q = 0; q < nc; q++)
      acc += sw[q] * x[ss[q] * HD + tid];
    __syncthreads();
  }
  float den = dsum;
  #pragma unroll
  for (int o = 16; o; o >>= 1) den += __shfl_xor_sync(0xFFFFFFFFu, den, o);
  if ((tid & 31) == 0) sh[tid >> 5] = den;
  __syncthreads();
  den = sh[0] + sh[1] + sh[2] + sh[3];
  g_xg[t * HD + tid] = acc / den;
}

// ============ kH2: H2 partials = xg @ U (64x128 tiles, split-K=2) ==========
__global__ __launch_bounds__(256, 2) void kH2() {
  __shared__ float As[2][16][65];
  __shared__ float Bs[2][16][129];
  int b = blockIdx.x;
  int tile = b % 288;
  int z = b / 288;
  int j0 = (tile % 12) * 128;
  int m0 = (tile / 12) * 64;
  int k0 = z * 64;
  int tid = threadIdx.x, tx = tid & 15, ty = tid >> 4;
  float acc[4][8];
  #pragma unroll
  for (int u = 0; u < 4; u++)
    #pragma unroll
    for (int w = 0; w < 8; w++) acc[u][w] = 0.f;
  auto load = [&](int buf, int kc) {
    #pragma unroll
    for (int l = tid; l < 64 * 16; l += 256) {
      int k = l & 15, m = l >> 4;
      As[buf][k][m] = g_xg[(m0 + m) * HD + k0 + kc + k];
    }
    #pragma unroll
    for (int l = tid; l < 16 * 128; l += 256) {
      int j = l & 127, k = l >> 7;
      Bs[buf][k][j] = g_U[(k0 + kc + k) * N + j0 + j];
    }
  };
  load(0, 0);
  __syncthreads();
  for (int c = 0; c < 4; c++) {
    int buf = c & 1;
    if (c < 3) load(buf ^ 1, (c + 1) * 16);
    #pragma unroll
    for (int kk = 0; kk < 16; kk++) {
      float ra[4], rb[8];
      #pragma unroll
      for (int u = 0; u < 4; u++) ra[u] = As[buf][kk][u * 16 + ty];
      #pragma unroll
      for (int w = 0; w < 8; w++) rb[w] = Bs[buf][kk][w * 16 + tx];
      #pragma unroll
      for (int u = 0; u < 4; u++)
        #pragma unroll
        for (int w = 0; w < 8; w++) acc[u][w] += ra[u] * rb[w];
    }
    __syncthreads();
  }
  float* outp = z ? g_H2b : g_H2;
  #pragma unroll
  for (int u = 0; u < 4; u++)
    #pragma unroll
    for (int w = 0; w < 8; w++)
      outp[(m0 + u * 16 + ty) * N + j0 + w * 16 + tx] = acc[u][w];
}

// == kF: per-row 2-hop mask + GATHER attention + radix-select + output ======
__global__ __launch_bounds__(256) void kF(const float* __restrict__ pas2,
                                          const float* __restrict__ pad2,
                                          const float* __restrict__ pb2,
                                          float* __restrict__ out, int wk) {
  int i = blockIdx.x, tid = threadIdx.x;
  __shared__ float v[N];
  __shared__ int vlist[N];
  __shared__ float scl[N];       // list-indexed scores
  __shared__ unsigned k32[N];    // list-indexed keys
  __shared__ unsigned mb[NW];
  __shared__ int wcnt[NW + 1];
  __shared__ int hist[256];
  __shared__ unsigned s_pfx;
  __shared__ int s_rem;

  float as2 = pas2[0], ad2 = pad2[0], b2 = pb2[0];

  if (tid < NW) {
    unsigned w = g_B[i * NW + tid];
    if (tid == (i >> 5)) w |= 1u << (i & 31);
    mb[tid] = w;
  }
  for (int j = tid; j < N; j += 256)
    v[j] = g_H2[i * N + j] + g_H2b[i * N + j] + g_c2[j];
  __syncthreads();
  // 1-hop list
  if (tid < NW) wcnt[tid] = __popc(mb[tid]);
  __syncthreads();
  if (tid == 0) {
    int s = 0;
    for (int w = 0; w < NW; w++) { int c = wcnt[w]; wcnt[w] = s; s += c; }
    wcnt[NW] = s;
  }
  __syncthreads();
  int nk = wcnt[NW];
  if (tid < NW) {
    unsigned b = mb[tid]; int o = wcnt[tid];
    while (b) { int t = __ffs(b) - 1; b &= b - 1; vlist[o++] = tid * 32 + t; }
  }
  __syncthreads();
  // 2-hop
  if (tid < 4 * NW) {
    int sy = tid / NW, cx = tid % NW;
    unsigned acc = 0u;
    for (int q = sy; q < nk; q += 4) acc |= g_B[vlist[q] * NW + cx];
    atomicOr(&mb[cx], acc);
  }
  __syncthreads();
  // valid list (ascending index order — stable tie-break depends on it)
  if (tid < NW) wcnt[tid] = __popc(mb[tid]);
  __syncthreads();
  if (tid == 0) {
    int s = 0;
    for (int w = 0; w < NW; w++) { int c = wcnt[w]; wcnt[w] = s; s += c; }
    wcnt[NW] = s;
  }
  __syncthreads();
  int nvv = wcnt[NW];
  if (tid < NW) {
    unsigned b = mb[tid]; int o = wcnt[tid];
    while (b) { int t = __ffs(b) - 1; b &= b - 1; vlist[o++] = tid * 32 + t; }
  }
  __syncthreads();
  // gather softmax: one thread per valid target, registers only
  for (int li = tid; li < nvv; li += 256) {
    int t = vlist[li];
    int p0 = g_offT[t], p1 = g_offT[t + 1];
    float adt = ad2 * v[t];
    float m = -3.4e38f;
    for (int p = p0; p < p1; p++) {
      int s = g_srcT[p];
      if ((mb[s >> 5] >> (s & 31)) & 1u)
        m = fmaxf(m, lrelu(as2 * v[s] + adt));
    }
    float den = 0.f, num = 0.f;
    for (int p = p0; p < p1; p++) {
      int s = g_srcT[p];
      if ((mb[s >> 5] >> (s & 31)) & 1u) {
        float vs = v[s];
        float w = expf(lrelu(as2 * vs + adt) - m);
        den += w;
        num += w * vs;
      }
    }
    float sc = num / fmaxf(den, 1e-12f) + b2;
    scl[li] = sc;
    k32[li] = fenc(sc);
  }
  int kk = (nvv + 1) >> 1;
  if (tid == 0) { s_rem = kk; s_pfx = 0u; }
  __syncthreads();
  // radix-select the kk-th largest key (4 rounds of 8 bits)
  for (int r = 0; r < 4; r++) {
    int shift = 24 - 8 * r;
    if (tid < 256) hist[tid] = 0;
    __syncthreads();
    unsigned pfx = s_pfx;
    for (int li = tid; li < nvv; li += 256) {
      unsigned key = k32[li];
      bool cand = (r == 0) || ((key >> (shift + 8)) == pfx);
      if (cand) atomicAdd(&hist[(key >> shift) & 255], 1);
    }
    __syncthreads();
    if (tid < 32) {
      int s = 0;
      #pragma unroll
      for (int u = 0; u < 8; u++) s += hist[tid * 8 + u];
      int cum = s;
      #pragma unroll
      for (int o = 1; o < 32; o <<= 1) {
        int t2 = __shfl_down_sync(0xFFFFFFFFu, cum, o);
        if (tid + o < 32) cum += t2;
      }
      int run = cum - s;            // count in buckets >= 8*(tid+1)
      int rem = s_rem;
      unsigned pfxold = s_pfx;
      int fb = -1, frem = 0;
      for (int bb = tid * 8 + 7; bb >= tid * 8; bb--) {
        int h = hist[bb];
        if (run < rem && rem <= run + h) { fb = bb; frem = rem - run; }
        run += h;
      }
      __syncwarp();
      if (fb >= 0) { s_pfx = (pfxold << 8) | (unsigned)fb; s_rem = frem; }
    }
    __syncthreads();
  }
  unsigned T = s_pfx;
  int rem = s_rem;
  // keep: key > T, or key == T with tie-rank (ascending index) < rem
  for (int li = tid; li < nvv; li += 256) {
    unsigned key = k32[li];
    bool keep = key > T;
    if (!keep && key == T) {
      int cnt = 0;
      for (int l2 = 0; l2 < li; l2++) cnt += (k32[l2] == T);
      keep = cnt < rem;
    }
    if (keep) {
      int j = vlist[li];
      float sj = scl[li];
      out[i * N + j] = 1.f / (1.f + expf(-sj));
      if (wk) out[N * N + i * N + j] = 1.f;
    }
  }
}

// ---------------- launch: forked-capture graph ----------------
extern "C" void kernel_launch(void* const* d_in, const int* in_sizes, int n_in,
                              void* d_out, int out_size) {
  const float* x   = (const float*)d_in[0];
  const float* xo  = (const float*)d_in[1];
  const int*   ei  = (const int*)d_in[2];
  const float* W1  = (const float*)d_in[4];
  const float* a1  = (const float*)d_in[5];
  const float* a2  = (const float*)d_in[6];
  const float* b1  = (const float*)d_in[7];
  const float* w2  = (const float*)d_in[8];
  const float* as2 = (const float*)d_in[9];
  const float* ad2 = (const float*)d_in[10];
  const float* b2  = (const float*)d_in[11];
  float* out = (float*)d_out;
  int wk = (out_size >= 2 * N * N) ? 1 : 0;

  // fork side branches off the (possibly capturing) default stream
  cudaEventRecord(g_hs.e0, 0);
  cudaStreamWaitEvent(g_hs.s1, g_hs.e0, 0);
  cudaStreamWaitEvent(g_hs.s2, g_hs.e0, 0);
  cudaStreamWaitEvent(g_hs.s3, g_hs.e0, 0);

  // s3: zero out + g_B
  kZero<<<512, 256, 0, g_hs.s3>>>(out, out_size);
  cudaEventRecord(g_hs.e3, g_hs.s3);

  // s1: vec1 -> sada
  kVec1<<<HD + N, 256, 0, g_hs.s1>>>(W1, a1, a2, b1, w2, xo);
  kSada<<<192, 256, 0, g_hs.s1>>>(x);
  cudaEventRecord(g_hs.e1, g_hs.s1);

  // s2: U partials -> U reduce
  kUp<<<24 * ZU, 256, 0, g_hs.s2>>>(W1, w2, xo);
  kUred<<<(HD * N) / 256, 256, 0, g_hs.s2>>>();
  cudaEventRecord(g_hs.e2, g_hs.s2);

  // s0 (default): critical path
  kCount<<<E2 / 256, 256>>>(ei);
  kScan<<<1, 256>>>();
  cudaStreamWaitEvent(0, g_hs.e3, 0);   // g_B zeroed before fill's atomicOr
  kFill<<<E2 / 256, 256>>>(ei);
  cudaStreamWaitEvent(0, g_hs.e1, 0);   // sada done before xg
  kXg<<<N, 128>>>(x);
  cudaStreamWaitEvent(0, g_hs.e2, 0);   // U ready before H2
  kH2<<<576, 256>>>();
  kF<<<N, 256>>>(as2, ad2, b2, out, wk);
}